// round 7
// baseline (speedup 1.0000x reference)
#include <cuda_runtime.h>
#include <math.h>

#define N_ENT 50000
#define N_REL 237
#define N_TYPE 4000
#define DE 100
#define NOUT 128
#define DT 200
#define DTP 224
#define N_EDGE 800000
#define BATCH 4096
#define NUM_FILT 32
#define CONV_W 60
#define POOL_W 30
#define FC_LEN 960
#define EPS 1e-5f

// ---------------- scratch ----------------
__device__ float g_h[N_ENT * NOUT];
__device__ float g_hd[N_ENT];
__device__ float g_hm[N_ENT];
__device__ float g_wa1[DE];
__device__ float g_wa2[DE];
__device__ float g_rproj[N_REL * NOUT];
__device__ float g_ra[N_REL];
__device__ float g_denom[N_ENT];
__device__ int   g_flag[N_ENT];
__device__ int   g_ecnt;
__device__ int   g_cs[N_EDGE];
__device__ int   g_cd[N_EDGE];
__device__ int   g_ct[N_EDGE];
__device__ float g_ex[N_EDGE];
__device__ float g_agg[N_ENT * NOUT];
__device__ float g_e[BATCH * NOUT];
__device__ float g_conv[BATCH * NUM_FILT * CONV_W];
__device__ float g_y[BATCH * DT];
__device__ float g_z[BATCH * DTP];              // relu(bn2), tf32-rounded, K-padded
__device__ float g_twc[N_TYPE * DTP];           // Tw tf32-rounded, K-padded
__device__ float g_fcwc[DT * FC_LEN];           // fc_w tf32-rounded
__device__ float g_bn1[4];
__device__ float g_bn3sum[NUM_FILT], g_bn3ss[NUM_FILT];
__device__ float g_bn3sc[NUM_FILT], g_bn3sh[NUM_FILT];
__device__ float g_bn2sc[DT], g_bn2sh[DT];

// ---------------- helpers ----------------
__device__ __forceinline__ unsigned f2tf(float x) {
    unsigned r;
    asm("cvt.rna.tf32.f32 %0, %1;" : "=r"(r) : "f"(x));
    return r;
}

__device__ __forceinline__ void mma_tf32(float c[4], const unsigned a[4], const unsigned b[2]) {
    asm volatile(
        "mma.sync.aligned.m16n8k8.row.col.f32.tf32.tf32.f32 "
        "{%0,%1,%2,%3}, {%4,%5,%6,%7}, {%8,%9}, {%0,%1,%2,%3};"
        : "+f"(c[0]), "+f"(c[1]), "+f"(c[2]), "+f"(c[3])
        : "r"(a[0]), "r"(a[1]), "r"(a[2]), "r"(a[3]), "r"(b[0]), "r"(b[1]));
}

// ---------------- small kernels ----------------

__global__ void k_zero() {
    int tid = blockIdx.x * blockDim.x + threadIdx.x;
    int stride = gridDim.x * blockDim.x;
    for (int i = tid; i < N_ENT; i += stride) { g_denom[i] = 0.f; g_flag[i] = 0; }
    if (tid == 0) g_ecnt = 0;
    if (tid < 2) g_bn1[tid] = 0.f;
    for (int i = tid; i < NUM_FILT; i += stride) { g_bn3sum[i] = 0.f; g_bn3ss[i] = 0.f; }
}

__global__ void k_flag(const int* __restrict__ xb) {
    int n = xb[blockIdx.x];
    if (threadIdx.x == 0) g_flag[n] = 1;
    g_agg[n * NOUT + threadIdx.x] = 0.f;
}

// compact edges whose dst is flagged (warp-aggregated atomics)
__global__ void k_compact(const int* __restrict__ ei, const int* __restrict__ et) {
    int e = blockIdx.x * blockDim.x + threadIdx.x;
    int lane = threadIdx.x & 31;
    int dst = -1;
    bool pred = false;
    if (e < N_EDGE) {
        dst = ei[N_EDGE + e];
        pred = (g_flag[dst] != 0);
    }
    unsigned mask = __ballot_sync(0xffffffffu, pred);
    if (mask == 0) return;
    int leader = __ffs(mask) - 1;
    int base = 0;
    if (lane == leader) base = atomicAdd(&g_ecnt, __popc(mask));
    base = __shfl_sync(0xffffffffu, base, leader);
    if (pred) {
        int pos = base + __popc(mask & ((1u << lane) - 1u));
        g_cs[pos] = ei[e];
        g_cd[pos] = dst;
        g_ct[pos] = et[e];
    }
}

// wa1 = W_f @ a1, wa2 = W_f @ a2   (warp per k-row)
__global__ void k_wa(const float* __restrict__ Wf, const float* __restrict__ av) {
    int k = blockIdx.x * 8 + (threadIdx.x >> 5);
    int lane = threadIdx.x & 31;
    if (k >= DE) return;
    float s1 = 0.f, s2 = 0.f;
#pragma unroll
    for (int q = 0; q < 4; q++) {
        int j = lane + q * 32;
        float w = Wf[k * NOUT + j];
        s1 += w * av[j];
        s2 += w * av[NOUT + j];
    }
#pragma unroll
    for (int o = 16; o > 0; o >>= 1) {
        s1 += __shfl_xor_sync(0xffffffffu, s1, o);
        s2 += __shfl_xor_sync(0xffffffffu, s2, o);
    }
    if (lane == 0) { g_hd[k] = 0.f; g_wa1[k] = s1; g_wa2[k] = s2; }
}

// h = Ew @ Wf (16 nodes/block) ; fused hd/hm
__global__ void k_h16(const float* __restrict__ Ew, const float* __restrict__ Wf) {
    int n0 = blockIdx.x * 16;
    int t = threadIdx.x;
    int jl = t & 31;
    int ng = t >> 5;
    __shared__ float er[16][DE];
    for (int i = t; i < 16 * DE; i += 128) er[i / DE][i % DE] = Ew[n0 * DE + i];
    __syncthreads();
    float acc[4][4];
#pragma unroll
    for (int a = 0; a < 4; a++)
#pragma unroll
        for (int b = 0; b < 4; b++) acc[a][b] = 0.f;
    for (int k = 0; k < DE; k++) {
        float w0 = Wf[k * NOUT + jl];
        float w1 = Wf[k * NOUT + jl + 32];
        float w2 = Wf[k * NOUT + jl + 64];
        float w3 = Wf[k * NOUT + jl + 96];
#pragma unroll
        for (int nn = 0; nn < 4; nn++) {
            float e = er[ng * 4 + nn][k];
            acc[nn][0] += e * w0;
            acc[nn][1] += e * w1;
            acc[nn][2] += e * w2;
            acc[nn][3] += e * w3;
        }
    }
#pragma unroll
    for (int nn = 0; nn < 4; nn++)
#pragma unroll
        for (int q = 0; q < 4; q++)
            g_h[(n0 + ng * 4 + nn) * NOUT + q * 32 + jl] = acc[nn][q];
    // fused hd/hm: 8 threads per node
    int oct = t >> 3, ol = t & 7;
    float s1 = 0.f, s2 = 0.f;
    for (int k = ol; k < DE; k += 8) {
        float v = er[oct][k];
        s1 += v * g_wa1[k];
        s2 += v * g_wa2[k];
    }
#pragma unroll
    for (int o = 4; o > 0; o >>= 1) {
        s1 += __shfl_xor_sync(0xffffffffu, s1, o);
        s2 += __shfl_xor_sync(0xffffffffu, s2, o);
    }
    if (ol == 0) { g_hd[n0 + oct] = s1; g_hm[n0 + oct] = s2; }
}

// rproj = R_w @ W_f ; ra = rproj . a2
__global__ void k_rproj(const float* __restrict__ Rw, const float* __restrict__ Wf,
                        const float* __restrict__ av) {
    int r = blockIdx.x, j = threadIdx.x;
    __shared__ float rr[DE];
    __shared__ float red[NOUT];
    if (j < DE) rr[j] = Rw[r * DE + j];
    __syncthreads();
    float acc = 0.f;
#pragma unroll 4
    for (int k = 0; k < DE; k++) acc += rr[k] * Wf[k * NOUT + j];
    g_rproj[r * NOUT + j] = acc;
    red[j] = acc * av[NOUT + j];
    __syncthreads();
    for (int s = 64; s > 0; s >>= 1) {
        if (j < s) red[j] += red[j + s];
        __syncthreads();
    }
    if (j == 0) g_ra[r] = red[0];
}

__global__ void k_score() {
    int tid = blockIdx.x * blockDim.x + threadIdx.x;
    int stride = gridDim.x * blockDim.x;
    int cnt = g_ecnt;
    for (int e = tid; e < cnt; e += stride) {
        int src = g_cs[e], dst = g_cd[e], t = g_ct[e];
        float s = g_hd[dst] + g_hm[src] - g_ra[t];
        s = (s >= 0.f) ? s : 0.2f * s;
        float ex = expf(s);
        g_ex[e] = ex;
        atomicAdd(&g_denom[dst], ex);
    }
}

__global__ void k_agg() {
    int w = (blockIdx.x * blockDim.x + threadIdx.x) >> 5;
    int nwarp = (gridDim.x * blockDim.x) >> 5;
    int lane = threadIdx.x & 31;
    int cnt = g_ecnt;
    for (int e = w; e < cnt; e += nwarp) {
        int src = g_cs[e], dst = g_cd[e], t = g_ct[e];
        float wt = g_ex[e] / (g_denom[dst] + 1e-16f);
        float4 a = reinterpret_cast<const float4*>(&g_h[src * NOUT])[lane];
        float4 b = reinterpret_cast<const float4*>(&g_rproj[t * NOUT])[lane];
        float4 v;
        v.x = wt * (a.x - b.x); v.y = wt * (a.y - b.y);
        v.z = wt * (a.z - b.z); v.w = wt * (a.w - b.w);
        float* p = &g_agg[dst * NOUT + lane * 4];
        asm volatile("red.global.add.v4.f32 [%0], {%1,%2,%3,%4};"
                     :: "l"(p), "f"(v.x), "f"(v.y), "f"(v.z), "f"(v.w) : "memory");
    }
}

__global__ void k_gather(const int* __restrict__ xb) {
    int b = blockIdx.x, j = threadIdx.x;
    __shared__ float r1[NOUT], r2[NOUT];
    float v = g_agg[xb[b] * NOUT + j];
    float e = (v > 0.f) ? v : expm1f(v);
    g_e[b * NOUT + j] = e;
    r1[j] = e;
    r2[j] = e * e;
    __syncthreads();
    for (int s = 64; s > 0; s >>= 1) {
        if (j < s) { r1[j] += r1[j + s]; r2[j] += r2[j + s]; }
        __syncthreads();
    }
    if (j == 0) { atomicAdd(&g_bn1[0], r1[0]); atomicAdd(&g_bn1[1], r2[0]); }
}

__global__ void k_bn1fin(const float* __restrict__ g, const float* __restrict__ b) {
    float cnt = (float)(BATCH * NOUT);
    float mean = g_bn1[0] / cnt;
    float var = g_bn1[1] / cnt - mean * mean;
    float inv = rsqrtf(var + EPS);
    float sc = g[0] * inv;
    g_bn1[2] = sc;
    g_bn1[3] = b[0] - sc * mean;
}

__global__ void k_conv(const float* __restrict__ cw, const float* __restrict__ cb) {
    int b = blockIdx.x, tid = threadIdx.x;
    __shared__ float es[NOUT];
    __shared__ float wsm[NUM_FILT * 9];
    __shared__ float co[NUM_FILT * CONV_W];
    float sc = g_bn1[2], sh = g_bn1[3];
    if (tid < NOUT) es[tid] = sc * g_e[b * NOUT + tid] + sh;
    for (int i = tid; i < NUM_FILT * 9; i += blockDim.x) wsm[i] = cw[i];
    __syncthreads();
    for (int i = tid; i < NUM_FILT * CONV_W; i += blockDim.x) {
        int c = i / CONV_W, w = i % CONV_W;
        float acc = cb[c];
#pragma unroll
        for (int k = 0; k < 9; k++) acc += wsm[c * 9 + k] * es[2 * w + k];
        co[i] = acc;
        g_conv[b * NUM_FILT * CONV_W + i] = acc;
    }
    __syncthreads();
    if (tid < NUM_FILT) {
        float s = 0.f, ss = 0.f;
        for (int w = 0; w < CONV_W; w++) {
            float v = co[tid * CONV_W + w];
            s += v; ss += v * v;
        }
        atomicAdd(&g_bn3sum[tid], s);
        atomicAdd(&g_bn3ss[tid], ss);
    }
}

__global__ void k_bn3fin(const float* __restrict__ g, const float* __restrict__ b) {
    int c = threadIdx.x;
    if (c >= NUM_FILT) return;
    float cnt = (float)(BATCH * CONV_W);
    float mean = g_bn3sum[c] / cnt;
    float var = g_bn3ss[c] / cnt - mean * mean;
    float inv = rsqrtf(var + EPS);
    float sc = g[c] * inv;
    g_bn3sc[c] = sc;
    g_bn3sh[c] = b[c] - sc * mean;
}

// prep: convert weights to tf32-rounded copies (padded K for Tw)
__global__ void k_prep_tw(const float* __restrict__ Tw) {
    int i = blockIdx.x * blockDim.x + threadIdx.x;
    if (i >= N_TYPE * DTP) return;
    int n = i / DTP, k = i % DTP;
    float v = (k < DT) ? Tw[n * DT + k] : 0.f;
    g_twc[i] = __uint_as_float(f2tf(v));
}

__global__ void k_prep_fcw(const float* __restrict__ fcw) {
    int i = blockIdx.x * blockDim.x + threadIdx.x;
    if (i >= DT * FC_LEN) return;
    g_fcwc[i] = __uint_as_float(f2tf(fcw[i]));
}

// ---------------- tf32 GEMM 1: fc  y[4096,200] = F[4096,960] @ fcw^T ----------------
// F built on the fly: bn3 + relu + maxpool over g_conv.
#define SAP 36
__global__ void __launch_bounds__(256) k_fc(const float* __restrict__ fcb) {
    __shared__ unsigned As[128 * SAP];
    __shared__ unsigned Bs[128 * SAP];
    int t = threadIdx.x;
    int warp = t >> 5, lane = t & 31;
    int wm = warp >> 2, wn = warp & 3;      // 2 x 4 warps
    int g = lane >> 2, tg = lane & 3;
    int m0 = blockIdx.x * 128;
    int n0 = blockIdx.y * 128;
    int lrow = t >> 1, lpart = (t & 1) * 16;

    float c[4][4][4];
#pragma unroll
    for (int i = 0; i < 4; i++)
#pragma unroll
        for (int j = 0; j < 4; j++)
#pragma unroll
            for (int q = 0; q < 4; q++) c[i][j][q] = 0.f;

    for (int kc = 0; kc < FC_LEN / 32; kc++) {
        int k0g = kc * 32;
        // stage A: pooled+bn3+relu features, tf32-rounded
        {
            int b = m0 + lrow;
            const float* crow = &g_conv[b * (NUM_FILT * CONV_W)];
#pragma unroll
            for (int q = 0; q < 16; q++) {
                int kk = k0g + lpart + q;
                int ch = kk / POOL_W, w = kk % POOL_W;
                float sc = g_bn3sc[ch], sh = g_bn3sh[ch];
                float x0 = crow[ch * CONV_W + 2 * w];
                float x1 = crow[ch * CONV_W + 2 * w + 1];
                float v = fmaxf(fmaxf(sc * x0 + sh, sc * x1 + sh), 0.f);
                As[lrow * SAP + lpart + q] = f2tf(v);
            }
        }
        // stage B: fcw rows (guard n<200)
        {
            int n = n0 + lrow;
            if (n < DT) {
                const float4* src = reinterpret_cast<const float4*>(&g_fcwc[n * FC_LEN + k0g + lpart]);
#pragma unroll
                for (int q = 0; q < 4; q++) {
                    float4 v = src[q];
                    Bs[lrow * SAP + lpart + q * 4 + 0] = __float_as_uint(v.x);
                    Bs[lrow * SAP + lpart + q * 4 + 1] = __float_as_uint(v.y);
                    Bs[lrow * SAP + lpart + q * 4 + 2] = __float_as_uint(v.z);
                    Bs[lrow * SAP + lpart + q * 4 + 3] = __float_as_uint(v.w);
                }
            } else {
#pragma unroll
                for (int q = 0; q < 16; q++) Bs[lrow * SAP + lpart + q] = 0u;
            }
        }
        __syncthreads();
#pragma unroll
        for (int kk = 0; kk < 4; kk++) {
            int k0 = kk * 8;
            unsigned ar[4][4], br[4][2];
#pragma unroll
            for (int mt = 0; mt < 4; mt++) {
                int r = wm * 64 + mt * 16 + g;
                ar[mt][0] = As[r * SAP + k0 + tg];
                ar[mt][1] = As[(r + 8) * SAP + k0 + tg];
                ar[mt][2] = As[r * SAP + k0 + tg + 4];
                ar[mt][3] = As[(r + 8) * SAP + k0 + tg + 4];
            }
#pragma unroll
            for (int nt = 0; nt < 4; nt++) {
                int r = wn * 32 + nt * 8 + g;
                br[nt][0] = Bs[r * SAP + k0 + tg];
                br[nt][1] = Bs[r * SAP + k0 + tg + 4];
            }
#pragma unroll
            for (int mt = 0; mt < 4; mt++)
#pragma unroll
                for (int nt = 0; nt < 4; nt++) mma_tf32(c[mt][nt], ar[mt], br[nt]);
        }
        __syncthreads();
    }
    // epilogue: y = c + fcb
#pragma unroll
    for (int mt = 0; mt < 4; mt++) {
        int mrow = m0 + wm * 64 + mt * 16 + g;
#pragma unroll
        for (int nt = 0; nt < 4; nt++) {
            int n = n0 + wn * 32 + nt * 8 + 2 * tg;
            if (n < DT)     g_y[mrow * DT + n]           = c[mt][nt][0] + fcb[n];
            if (n + 1 < DT) g_y[mrow * DT + n + 1]       = c[mt][nt][1] + fcb[n + 1];
            if (n < DT)     g_y[(mrow + 8) * DT + n]     = c[mt][nt][2] + fcb[n];
            if (n + 1 < DT) g_y[(mrow + 8) * DT + n + 1] = c[mt][nt][3] + fcb[n + 1];
        }
    }
}

// bn2 stats + finalize: one block per feature column
__global__ void k_bn2(const float* __restrict__ g, const float* __restrict__ b) {
    int k = blockIdx.x, tid = threadIdx.x;
    __shared__ float r1[128], r2[128];
    float s = 0.f, ss = 0.f;
    for (int i = tid; i < BATCH; i += 128) {
        float v = g_y[i * DT + k];
        s += v; ss += v * v;
    }
    r1[tid] = s; r2[tid] = ss;
    __syncthreads();
    for (int o = 64; o > 0; o >>= 1) {
        if (tid < o) { r1[tid] += r1[tid + o]; r2[tid] += r2[tid + o]; }
        __syncthreads();
    }
    if (tid == 0) {
        float cnt = (float)BATCH;
        float mean = r1[0] / cnt;
        float var = r2[0] / cnt - mean * mean;
        float inv = rsqrtf(var + EPS);
        float sc = g[k] * inv;
        g_bn2sc[k] = sc;
        g_bn2sh[k] = b[k] - sc * mean;
    }
}

// z = relu(bn2(y)), tf32-rounded, zero-padded to DTP
__global__ void k_bn2apply() {
    int i = blockIdx.x * blockDim.x + threadIdx.x;
    if (i >= BATCH * DTP) return;
    int k = i % DTP;
    float v = 0.f;
    if (k < DT) v = fmaxf(g_bn2sc[k] * g_y[(i / DTP) * DT + k] + g_bn2sh[k], 0.f);
    g_z[i] = __uint_as_float(f2tf(v));
}

// ---------------- tf32 GEMM 2: out = sigmoid(Z @ Tw^T + bias) ----------------
__global__ void __launch_bounds__(256) k_out(const float* __restrict__ bbias,
                                             float* __restrict__ out) {
    __shared__ unsigned As[128 * SAP];
    __shared__ unsigned Bs[128 * SAP];
    int t = threadIdx.x;
    int warp = t >> 5, lane = t & 31;
    int wm = warp >> 2, wn = warp & 3;
    int g = lane >> 2, tg = lane & 3;
    int m0 = blockIdx.x * 128;
    int n0 = blockIdx.y * 128;
    int lrow = t >> 1, lpart = (t & 1) * 16;

    float c[4][4][4];
#pragma unroll
    for (int i = 0; i < 4; i++)
#pragma unroll
        for (int j = 0; j < 4; j++)
#pragma unroll
            for (int q = 0; q < 4; q++) c[i][j][q] = 0.f;

    for (int kc = 0; kc < DTP / 32; kc++) {
        int k0g = kc * 32;
        {
            const float4* src = reinterpret_cast<const float4*>(&g_z[(m0 + lrow) * DTP + k0g + lpart]);
#pragma unroll
            for (int q = 0; q < 4; q++) {
                float4 v = src[q];
                As[lrow * SAP + lpart + q * 4 + 0] = __float_as_uint(v.x);
                As[lrow * SAP + lpart + q * 4 + 1] = __float_as_uint(v.y);
                As[lrow * SAP + lpart + q * 4 + 2] = __float_as_uint(v.z);
                As[lrow * SAP + lpart + q * 4 + 3] = __float_as_uint(v.w);
            }
        }
        {
            int n = n0 + lrow;
            if (n < N_TYPE) {
                const float4* src = reinterpret_cast<const float4*>(&g_twc[n * DTP + k0g + lpart]);
#pragma unroll
                for (int q = 0; q < 4; q++) {
                    float4 v = src[q];
                    Bs[lrow * SAP + lpart + q * 4 + 0] = __float_as_uint(v.x);
                    Bs[lrow * SAP + lpart + q * 4 + 1] = __float_as_uint(v.y);
                    Bs[lrow * SAP + lpart + q * 4 + 2] = __float_as_uint(v.z);
                    Bs[lrow * SAP + lpart + q * 4 + 3] = __float_as_uint(v.w);
                }
            } else {
#pragma unroll
                for (int q = 0; q < 16; q++) Bs[lrow * SAP + lpart + q] = 0u;
            }
        }
        __syncthreads();
#pragma unroll
        for (int kk = 0; kk < 4; kk++) {
            int k0 = kk * 8;
            unsigned ar[4][4], br[4][2];
#pragma unroll
            for (int mt = 0; mt < 4; mt++) {
                int r = wm * 64 + mt * 16 + g;
                ar[mt][0] = As[r * SAP + k0 + tg];
                ar[mt][1] = As[(r + 8) * SAP + k0 + tg];
                ar[mt][2] = As[r * SAP + k0 + tg + 4];
                ar[mt][3] = As[(r + 8) * SAP + k0 + tg + 4];
            }
#pragma unroll
            for (int nt = 0; nt < 4; nt++) {
                int r = wn * 32 + nt * 8 + g;
                br[nt][0] = Bs[r * SAP + k0 + tg];
                br[nt][1] = Bs[r * SAP + k0 + tg + 4];
            }
#pragma unroll
            for (int mt = 0; mt < 4; mt++)
#pragma unroll
                for (int nt = 0; nt < 4; nt++) mma_tf32(c[mt][nt], ar[mt], br[nt]);
        }
        __syncthreads();
    }
#pragma unroll
    for (int mt = 0; mt < 4; mt++) {
        int mrow = m0 + wm * 64 + mt * 16 + g;
#pragma unroll
        for (int nt = 0; nt < 4; nt++) {
            int n = n0 + wn * 32 + nt * 8 + 2 * tg;
            if (n < N_TYPE) {
                float b0 = bbias[n];
                out[mrow * N_TYPE + n] = 1.f / (1.f + expf(-(c[mt][nt][0] + b0)));
                out[(mrow + 8) * N_TYPE + n] = 1.f / (1.f + expf(-(c[mt][nt][2] + b0)));
            }
            if (n + 1 < N_TYPE) {
                float b1 = bbias[n + 1];
                out[mrow * N_TYPE + n + 1] = 1.f / (1.f + expf(-(c[mt][nt][1] + b1)));
                out[(mrow + 8) * N_TYPE + n + 1] = 1.f / (1.f + expf(-(c[mt][nt][3] + b1)));
            }
        }
    }
}

// ---------------- launch ----------------
extern "C" void kernel_launch(void* const* d_in, const int* in_sizes, int n_in,
                              void* d_out, int out_size) {
    const int* xb = (const int*)d_in[0];
    const int* ei = (const int*)d_in[1];
    const int* et = (const int*)d_in[2];
    const float* Ew = (const float*)d_in[3];
    const float* Rw = (const float*)d_in[4];
    const float* Tw = (const float*)d_in[5];
    const float* Wf = (const float*)d_in[6];
    const float* av = (const float*)d_in[7];
    const float* cw = (const float*)d_in[8];
    const float* cb = (const float*)d_in[9];
    const float* b1g = (const float*)d_in[10];
    const float* b1b = (const float*)d_in[11];
    const float* b3g = (const float*)d_in[12];
    const float* b3b = (const float*)d_in[13];
    const float* b2g = (const float*)d_in[14];
    const float* b2b = (const float*)d_in[15];
    const float* fcw = (const float*)d_in[16];
    const float* fcb = (const float*)d_in[17];
    const float* bbias = (const float*)d_in[18];
    float* out = (float*)d_out;

    k_zero<<<512, 256>>>();
    k_flag<<<BATCH, NOUT>>>(xb);
    k_compact<<<(N_EDGE + 255) / 256, 256>>>(ei, et);
    k_wa<<<13, 256>>>(Wf, av);
    k_h16<<<N_ENT / 16, 128>>>(Ew, Wf);
    k_rproj<<<N_REL, NOUT>>>(Rw, Wf, av);
    k_score<<<512, 256>>>();
    k_agg<<<1024, 256>>>();
    k_gather<<<BATCH, NOUT>>>(xb);
    k_bn1fin<<<1, 1>>>(b1g, b1b);
    k_conv<<<BATCH, 256>>>(cw, cb);
    k_bn3fin<<<1, 32>>>(b3g, b3b);
    k_prep_fcw<<<(DT * FC_LEN + 255) / 256, 256>>>(fcw);
    {
        dim3 gg(BATCH / 128, 2);
        k_fc<<<gg, 256>>>(fcb);
    }
    k_bn2<<<DT, 128>>>(b2g, b2b);
    k_bn2apply<<<(BATCH * DTP + 255) / 256, 256>>>();
    k_prep_tw<<<(N_TYPE * DTP + 255) / 256, 256>>>(Tw);
    {
        dim3 gg(BATCH / 128, (N_TYPE + 127) / 128);
        k_out<<<gg, 256>>>(bbias, out);
    }
}

// round 8
// speedup vs baseline: 1.0004x; 1.0004x over previous
#include <cuda_runtime.h>
#include <math.h>

#define N_ENT 50000
#define N_REL 237
#define N_TYPE 4000
#define DE 100
#define NOUT 128
#define DT 200
#define DTP 224
#define N_EDGE 800000
#define BATCH 4096
#define NUM_FILT 32
#define CONV_W 60
#define POOL_W 30
#define FC_LEN 960
#define EPS 1e-5f

// ---------------- scratch ----------------
__device__ float g_h[N_ENT * NOUT];
__device__ float g_hd[N_ENT];
__device__ float g_hm[N_ENT];
__device__ float g_wa1[DE];
__device__ float g_wa2[DE];
__device__ float g_rproj[N_REL * NOUT];
__device__ float g_ra[N_REL];
__device__ float g_denom[N_ENT];
__device__ int   g_flag[N_ENT];
__device__ int   g_ecnt;
__device__ int   g_cs[N_EDGE];
__device__ int   g_cd[N_EDGE];
__device__ int   g_ct[N_EDGE];
__device__ float g_ex[N_EDGE];
__device__ float g_agg[N_ENT * NOUT];
__device__ float g_e[BATCH * NOUT];
__device__ float g_conv[BATCH * NUM_FILT * CONV_W];
__device__ float g_y[BATCH * DT];
__device__ float g_z[BATCH * DTP];              // relu(bn2), tf32-rounded, K-padded
__device__ float g_twc[N_TYPE * DTP];           // Tw tf32-rounded, K-padded
__device__ float g_fcwc[DT * FC_LEN];           // fc_w tf32-rounded
__device__ float g_bn1[4];
__device__ float g_bn3sum[NUM_FILT], g_bn3ss[NUM_FILT];
__device__ float g_bn3sc[NUM_FILT], g_bn3sh[NUM_FILT];
__device__ float g_bn2sc[DT], g_bn2sh[DT];

// ---------------- helpers ----------------
__device__ __forceinline__ unsigned f2tf(float x) {
    unsigned r;
    asm("cvt.rna.tf32.f32 %0, %1;" : "=r"(r) : "f"(x));
    return r;
}

__device__ __forceinline__ void mma_tf32(float c[4], const unsigned a[4], const unsigned b[2]) {
    asm volatile(
        "mma.sync.aligned.m16n8k8.row.col.f32.tf32.tf32.f32 "
        "{%0,%1,%2,%3}, {%4,%5,%6,%7}, {%8,%9}, {%0,%1,%2,%3};"
        : "+f"(c[0]), "+f"(c[1]), "+f"(c[2]), "+f"(c[3])
        : "r"(a[0]), "r"(a[1]), "r"(a[2]), "r"(a[3]), "r"(b[0]), "r"(b[1]));
}

// ---------------- small kernels ----------------

__global__ void k_zero() {
    int tid = blockIdx.x * blockDim.x + threadIdx.x;
    int stride = gridDim.x * blockDim.x;
    for (int i = tid; i < N_ENT; i += stride) { g_denom[i] = 0.f; g_flag[i] = 0; }
    if (tid == 0) g_ecnt = 0;
    if (tid < 2) g_bn1[tid] = 0.f;
    for (int i = tid; i < NUM_FILT; i += stride) { g_bn3sum[i] = 0.f; g_bn3ss[i] = 0.f; }
}

__global__ void k_flag(const int* __restrict__ xb) {
    int n = xb[blockIdx.x];
    if (threadIdx.x == 0) g_flag[n] = 1;
    g_agg[n * NOUT + threadIdx.x] = 0.f;
}

// compact edges whose dst is flagged (warp-aggregated atomics)
__global__ void k_compact(const int* __restrict__ ei, const int* __restrict__ et) {
    int e = blockIdx.x * blockDim.x + threadIdx.x;
    int lane = threadIdx.x & 31;
    int dst = -1;
    bool pred = false;
    if (e < N_EDGE) {
        dst = ei[N_EDGE + e];
        pred = (g_flag[dst] != 0);
    }
    unsigned mask = __ballot_sync(0xffffffffu, pred);
    if (mask == 0) return;
    int leader = __ffs(mask) - 1;
    int base = 0;
    if (lane == leader) base = atomicAdd(&g_ecnt, __popc(mask));
    base = __shfl_sync(0xffffffffu, base, leader);
    if (pred) {
        int pos = base + __popc(mask & ((1u << lane) - 1u));
        g_cs[pos] = ei[e];
        g_cd[pos] = dst;
        g_ct[pos] = et[e];
    }
}

// wa1 = W_f @ a1, wa2 = W_f @ a2   (warp per k-row)
__global__ void k_wa(const float* __restrict__ Wf, const float* __restrict__ av) {
    int k = blockIdx.x * 8 + (threadIdx.x >> 5);
    int lane = threadIdx.x & 31;
    if (k >= DE) return;
    float s1 = 0.f, s2 = 0.f;
#pragma unroll
    for (int q = 0; q < 4; q++) {
        int j = lane + q * 32;
        float w = Wf[k * NOUT + j];
        s1 += w * av[j];
        s2 += w * av[NOUT + j];
    }
#pragma unroll
    for (int o = 16; o > 0; o >>= 1) {
        s1 += __shfl_xor_sync(0xffffffffu, s1, o);
        s2 += __shfl_xor_sync(0xffffffffu, s2, o);
    }
    if (lane == 0) { g_hd[k] = 0.f; g_wa1[k] = s1; g_wa2[k] = s2; }
}

// h = Ew @ Wf (16 nodes/block) ; fused hd/hm
__global__ void k_h16(const float* __restrict__ Ew, const float* __restrict__ Wf) {
    int n0 = blockIdx.x * 16;
    int t = threadIdx.x;
    int jl = t & 31;
    int ng = t >> 5;
    __shared__ float er[16][DE];
    for (int i = t; i < 16 * DE; i += 128) er[i / DE][i % DE] = Ew[n0 * DE + i];
    __syncthreads();
    float acc[4][4];
#pragma unroll
    for (int a = 0; a < 4; a++)
#pragma unroll
        for (int b = 0; b < 4; b++) acc[a][b] = 0.f;
    for (int k = 0; k < DE; k++) {
        float w0 = Wf[k * NOUT + jl];
        float w1 = Wf[k * NOUT + jl + 32];
        float w2 = Wf[k * NOUT + jl + 64];
        float w3 = Wf[k * NOUT + jl + 96];
#pragma unroll
        for (int nn = 0; nn < 4; nn++) {
            float e = er[ng * 4 + nn][k];
            acc[nn][0] += e * w0;
            acc[nn][1] += e * w1;
            acc[nn][2] += e * w2;
            acc[nn][3] += e * w3;
        }
    }
#pragma unroll
    for (int nn = 0; nn < 4; nn++)
#pragma unroll
        for (int q = 0; q < 4; q++)
            g_h[(n0 + ng * 4 + nn) * NOUT + q * 32 + jl] = acc[nn][q];
    // fused hd/hm: 8 threads per node
    int oct = t >> 3, ol = t & 7;
    float s1 = 0.f, s2 = 0.f;
    for (int k = ol; k < DE; k += 8) {
        float v = er[oct][k];
        s1 += v * g_wa1[k];
        s2 += v * g_wa2[k];
    }
#pragma unroll
    for (int o = 4; o > 0; o >>= 1) {
        s1 += __shfl_xor_sync(0xffffffffu, s1, o);
        s2 += __shfl_xor_sync(0xffffffffu, s2, o);
    }
    if (ol == 0) { g_hd[n0 + oct] = s1; g_hm[n0 + oct] = s2; }
}

// rproj = R_w @ W_f ; ra = rproj . a2
__global__ void k_rproj(const float* __restrict__ Rw, const float* __restrict__ Wf,
                        const float* __restrict__ av) {
    int r = blockIdx.x, j = threadIdx.x;
    __shared__ float rr[DE];
    __shared__ float red[NOUT];
    if (j < DE) rr[j] = Rw[r * DE + j];
    __syncthreads();
    float acc = 0.f;
#pragma unroll 4
    for (int k = 0; k < DE; k++) acc += rr[k] * Wf[k * NOUT + j];
    g_rproj[r * NOUT + j] = acc;
    red[j] = acc * av[NOUT + j];
    __syncthreads();
    for (int s = 64; s > 0; s >>= 1) {
        if (j < s) red[j] += red[j + s];
        __syncthreads();
    }
    if (j == 0) g_ra[r] = red[0];
}

__global__ void k_score() {
    int tid = blockIdx.x * blockDim.x + threadIdx.x;
    int stride = gridDim.x * blockDim.x;
    int cnt = g_ecnt;
    for (int e = tid; e < cnt; e += stride) {
        int src = g_cs[e], dst = g_cd[e], t = g_ct[e];
        float s = g_hd[dst] + g_hm[src] - g_ra[t];
        s = (s >= 0.f) ? s : 0.2f * s;
        float ex = expf(s);
        g_ex[e] = ex;
        atomicAdd(&g_denom[dst], ex);
    }
}

__global__ void k_agg() {
    int w = (blockIdx.x * blockDim.x + threadIdx.x) >> 5;
    int nwarp = (gridDim.x * blockDim.x) >> 5;
    int lane = threadIdx.x & 31;
    int cnt = g_ecnt;
    for (int e = w; e < cnt; e += nwarp) {
        int src = g_cs[e], dst = g_cd[e], t = g_ct[e];
        float wt = g_ex[e] / (g_denom[dst] + 1e-16f);
        float4 a = reinterpret_cast<const float4*>(&g_h[src * NOUT])[lane];
        float4 b = reinterpret_cast<const float4*>(&g_rproj[t * NOUT])[lane];
        float4 v;
        v.x = wt * (a.x - b.x); v.y = wt * (a.y - b.y);
        v.z = wt * (a.z - b.z); v.w = wt * (a.w - b.w);
        float* p = &g_agg[dst * NOUT + lane * 4];
        asm volatile("red.global.add.v4.f32 [%0], {%1,%2,%3,%4};"
                     :: "l"(p), "f"(v.x), "f"(v.y), "f"(v.z), "f"(v.w) : "memory");
    }
}

__global__ void k_gather(const int* __restrict__ xb) {
    int b = blockIdx.x, j = threadIdx.x;
    __shared__ float r1[NOUT], r2[NOUT];
    float v = g_agg[xb[b] * NOUT + j];
    float e = (v > 0.f) ? v : expm1f(v);
    g_e[b * NOUT + j] = e;
    r1[j] = e;
    r2[j] = e * e;
    __syncthreads();
    for (int s = 64; s > 0; s >>= 1) {
        if (j < s) { r1[j] += r1[j + s]; r2[j] += r2[j + s]; }
        __syncthreads();
    }
    if (j == 0) { atomicAdd(&g_bn1[0], r1[0]); atomicAdd(&g_bn1[1], r2[0]); }
}

__global__ void k_bn1fin(const float* __restrict__ g, const float* __restrict__ b) {
    float cnt = (float)(BATCH * NOUT);
    float mean = g_bn1[0] / cnt;
    float var = g_bn1[1] / cnt - mean * mean;
    float inv = rsqrtf(var + EPS);
    float sc = g[0] * inv;
    g_bn1[2] = sc;
    g_bn1[3] = b[0] - sc * mean;
}

__global__ void k_conv(const float* __restrict__ cw, const float* __restrict__ cb) {
    int b = blockIdx.x, tid = threadIdx.x;
    __shared__ float es[NOUT];
    __shared__ float wsm[NUM_FILT * 9];
    __shared__ float co[NUM_FILT * CONV_W];
    float sc = g_bn1[2], sh = g_bn1[3];
    if (tid < NOUT) es[tid] = sc * g_e[b * NOUT + tid] + sh;
    for (int i = tid; i < NUM_FILT * 9; i += blockDim.x) wsm[i] = cw[i];
    __syncthreads();
    for (int i = tid; i < NUM_FILT * CONV_W; i += blockDim.x) {
        int c = i / CONV_W, w = i % CONV_W;
        float acc = cb[c];
#pragma unroll
        for (int k = 0; k < 9; k++) acc += wsm[c * 9 + k] * es[2 * w + k];
        co[i] = acc;
        g_conv[b * NUM_FILT * CONV_W + i] = acc;
    }
    __syncthreads();
    if (tid < NUM_FILT) {
        float s = 0.f, ss = 0.f;
        for (int w = 0; w < CONV_W; w++) {
            float v = co[tid * CONV_W + w];
            s += v; ss += v * v;
        }
        atomicAdd(&g_bn3sum[tid], s);
        atomicAdd(&g_bn3ss[tid], ss);
    }
}

__global__ void k_bn3fin(const float* __restrict__ g, const float* __restrict__ b) {
    int c = threadIdx.x;
    if (c >= NUM_FILT) return;
    float cnt = (float)(BATCH * CONV_W);
    float mean = g_bn3sum[c] / cnt;
    float var = g_bn3ss[c] / cnt - mean * mean;
    float inv = rsqrtf(var + EPS);
    float sc = g[c] * inv;
    g_bn3sc[c] = sc;
    g_bn3sh[c] = b[c] - sc * mean;
}

// prep: convert weights to tf32-rounded copies (padded K for Tw)
__global__ void k_prep_tw(const float* __restrict__ Tw) {
    int i = blockIdx.x * blockDim.x + threadIdx.x;
    if (i >= N_TYPE * DTP) return;
    int n = i / DTP, k = i % DTP;
    float v = (k < DT) ? Tw[n * DT + k] : 0.f;
    g_twc[i] = __uint_as_float(f2tf(v));
}

__global__ void k_prep_fcw(const float* __restrict__ fcw) {
    int i = blockIdx.x * blockDim.x + threadIdx.x;
    if (i >= DT * FC_LEN) return;
    g_fcwc[i] = __uint_as_float(f2tf(fcw[i]));
}

// ---------------- tf32 GEMM 1: fc  y[4096,200] = F[4096,960] @ fcw^T ----------------
// F built on the fly: bn3 + relu + maxpool over g_conv.
#define SAP 36
__global__ void __launch_bounds__(256) k_fc(const float* __restrict__ fcb) {
    __shared__ unsigned As[128 * SAP];
    __shared__ unsigned Bs[128 * SAP];
    int t = threadIdx.x;
    int warp = t >> 5, lane = t & 31;
    int wm = warp >> 2, wn = warp & 3;      // 2 x 4 warps
    int g = lane >> 2, tg = lane & 3;
    int m0 = blockIdx.x * 128;
    int n0 = blockIdx.y * 128;
    int lrow = t >> 1, lpart = (t & 1) * 16;

    float c[4][4][4];
#pragma unroll
    for (int i = 0; i < 4; i++)
#pragma unroll
        for (int j = 0; j < 4; j++)
#pragma unroll
            for (int q = 0; q < 4; q++) c[i][j][q] = 0.f;

    for (int kc = 0; kc < FC_LEN / 32; kc++) {
        int k0g = kc * 32;
        // stage A: pooled+bn3+relu features, tf32-rounded
        {
            int b = m0 + lrow;
            const float* crow = &g_conv[b * (NUM_FILT * CONV_W)];
#pragma unroll
            for (int q = 0; q < 16; q++) {
                int kk = k0g + lpart + q;
                int ch = kk / POOL_W, w = kk % POOL_W;
                float sc = g_bn3sc[ch], sh = g_bn3sh[ch];
                float x0 = crow[ch * CONV_W + 2 * w];
                float x1 = crow[ch * CONV_W + 2 * w + 1];
                float v = fmaxf(fmaxf(sc * x0 + sh, sc * x1 + sh), 0.f);
                As[lrow * SAP + lpart + q] = f2tf(v);
            }
        }
        // stage B: fcw rows (guard n<200)
        {
            int n = n0 + lrow;
            if (n < DT) {
                const float4* src = reinterpret_cast<const float4*>(&g_fcwc[n * FC_LEN + k0g + lpart]);
#pragma unroll
                for (int q = 0; q < 4; q++) {
                    float4 v = src[q];
                    Bs[lrow * SAP + lpart + q * 4 + 0] = __float_as_uint(v.x);
                    Bs[lrow * SAP + lpart + q * 4 + 1] = __float_as_uint(v.y);
                    Bs[lrow * SAP + lpart + q * 4 + 2] = __float_as_uint(v.z);
                    Bs[lrow * SAP + lpart + q * 4 + 3] = __float_as_uint(v.w);
                }
            } else {
#pragma unroll
                for (int q = 0; q < 16; q++) Bs[lrow * SAP + lpart + q] = 0u;
            }
        }
        __syncthreads();
#pragma unroll
        for (int kk = 0; kk < 4; kk++) {
            int k0 = kk * 8;
            unsigned ar[4][4], br[4][2];
#pragma unroll
            for (int mt = 0; mt < 4; mt++) {
                int r = wm * 64 + mt * 16 + g;
                ar[mt][0] = As[r * SAP + k0 + tg];
                ar[mt][1] = As[(r + 8) * SAP + k0 + tg];
                ar[mt][2] = As[r * SAP + k0 + tg + 4];
                ar[mt][3] = As[(r + 8) * SAP + k0 + tg + 4];
            }
#pragma unroll
            for (int nt = 0; nt < 4; nt++) {
                int r = wn * 32 + nt * 8 + g;
                br[nt][0] = Bs[r * SAP + k0 + tg];
                br[nt][1] = Bs[r * SAP + k0 + tg + 4];
            }
#pragma unroll
            for (int mt = 0; mt < 4; mt++)
#pragma unroll
                for (int nt = 0; nt < 4; nt++) mma_tf32(c[mt][nt], ar[mt], br[nt]);
        }
        __syncthreads();
    }
    // epilogue: y = c + fcb
#pragma unroll
    for (int mt = 0; mt < 4; mt++) {
        int mrow = m0 + wm * 64 + mt * 16 + g;
#pragma unroll
        for (int nt = 0; nt < 4; nt++) {
            int n = n0 + wn * 32 + nt * 8 + 2 * tg;
            if (n < DT)     g_y[mrow * DT + n]           = c[mt][nt][0] + fcb[n];
            if (n + 1 < DT) g_y[mrow * DT + n + 1]       = c[mt][nt][1] + fcb[n + 1];
            if (n < DT)     g_y[(mrow + 8) * DT + n]     = c[mt][nt][2] + fcb[n];
            if (n + 1 < DT) g_y[(mrow + 8) * DT + n + 1] = c[mt][nt][3] + fcb[n + 1];
        }
    }
}

// bn2 stats + finalize: one block per feature column
__global__ void k_bn2(const float* __restrict__ g, const float* __restrict__ b) {
    int k = blockIdx.x, tid = threadIdx.x;
    __shared__ float r1[128], r2[128];
    float s = 0.f, ss = 0.f;
    for (int i = tid; i < BATCH; i += 128) {
        float v = g_y[i * DT + k];
        s += v; ss += v * v;
    }
    r1[tid] = s; r2[tid] = ss;
    __syncthreads();
    for (int o = 64; o > 0; o >>= 1) {
        if (tid < o) { r1[tid] += r1[tid + o]; r2[tid] += r2[tid + o]; }
        __syncthreads();
    }
    if (tid == 0) {
        float cnt = (float)BATCH;
        float mean = r1[0] / cnt;
        float var = r2[0] / cnt - mean * mean;
        float inv = rsqrtf(var + EPS);
        float sc = g[k] * inv;
        g_bn2sc[k] = sc;
        g_bn2sh[k] = b[k] - sc * mean;
    }
}

// z = relu(bn2(y)), tf32-rounded, zero-padded to DTP
__global__ void k_bn2apply() {
    int i = blockIdx.x * blockDim.x + threadIdx.x;
    if (i >= BATCH * DTP) return;
    int k = i % DTP;
    float v = 0.f;
    if (k < DT) v = fmaxf(g_bn2sc[k] * g_y[(i / DTP) * DT + k] + g_bn2sh[k], 0.f);
    g_z[i] = __uint_as_float(f2tf(v));
}

// ---------------- tf32 GEMM 2: out = sigmoid(Z @ Tw^T + bias) ----------------
__global__ void __launch_bounds__(256) k_out(const float* __restrict__ bbias,
                                             float* __restrict__ out) {
    __shared__ unsigned As[128 * SAP];
    __shared__ unsigned Bs[128 * SAP];
    int t = threadIdx.x;
    int warp = t >> 5, lane = t & 31;
    int wm = warp >> 2, wn = warp & 3;
    int g = lane >> 2, tg = lane & 3;
    int m0 = blockIdx.x * 128;
    int n0 = blockIdx.y * 128;
    int lrow = t >> 1, lpart = (t & 1) * 16;

    float c[4][4][4];
#pragma unroll
    for (int i = 0; i < 4; i++)
#pragma unroll
        for (int j = 0; j < 4; j++)
#pragma unroll
            for (int q = 0; q < 4; q++) c[i][j][q] = 0.f;

    for (int kc = 0; kc < DTP / 32; kc++) {
        int k0g = kc * 32;
        {
            const float4* src = reinterpret_cast<const float4*>(&g_z[(m0 + lrow) * DTP + k0g + lpart]);
#pragma unroll
            for (int q = 0; q < 4; q++) {
                float4 v = src[q];
                As[lrow * SAP + lpart + q * 4 + 0] = __float_as_uint(v.x);
                As[lrow * SAP + lpart + q * 4 + 1] = __float_as_uint(v.y);
                As[lrow * SAP + lpart + q * 4 + 2] = __float_as_uint(v.z);
                As[lrow * SAP + lpart + q * 4 + 3] = __float_as_uint(v.w);
            }
        }
        {
            int n = n0 + lrow;
            if (n < N_TYPE) {
                const float4* src = reinterpret_cast<const float4*>(&g_twc[n * DTP + k0g + lpart]);
#pragma unroll
                for (int q = 0; q < 4; q++) {
                    float4 v = src[q];
                    Bs[lrow * SAP + lpart + q * 4 + 0] = __float_as_uint(v.x);
                    Bs[lrow * SAP + lpart + q * 4 + 1] = __float_as_uint(v.y);
                    Bs[lrow * SAP + lpart + q * 4 + 2] = __float_as_uint(v.z);
                    Bs[lrow * SAP + lpart + q * 4 + 3] = __float_as_uint(v.w);
                }
            } else {
#pragma unroll
                for (int q = 0; q < 16; q++) Bs[lrow * SAP + lpart + q] = 0u;
            }
        }
        __syncthreads();
#pragma unroll
        for (int kk = 0; kk < 4; kk++) {
            int k0 = kk * 8;
            unsigned ar[4][4], br[4][2];
#pragma unroll
            for (int mt = 0; mt < 4; mt++) {
                int r = wm * 64 + mt * 16 + g;
                ar[mt][0] = As[r * SAP + k0 + tg];
                ar[mt][1] = As[(r + 8) * SAP + k0 + tg];
                ar[mt][2] = As[r * SAP + k0 + tg + 4];
                ar[mt][3] = As[(r + 8) * SAP + k0 + tg + 4];
            }
#pragma unroll
            for (int nt = 0; nt < 4; nt++) {
                int r = wn * 32 + nt * 8 + g;
                br[nt][0] = Bs[r * SAP + k0 + tg];
                br[nt][1] = Bs[r * SAP + k0 + tg + 4];
            }
#pragma unroll
            for (int mt = 0; mt < 4; mt++)
#pragma unroll
                for (int nt = 0; nt < 4; nt++) mma_tf32(c[mt][nt], ar[mt], br[nt]);
        }
        __syncthreads();
    }
#pragma unroll
    for (int mt = 0; mt < 4; mt++) {
        int mrow = m0 + wm * 64 + mt * 16 + g;
#pragma unroll
        for (int nt = 0; nt < 4; nt++) {
            int n = n0 + wn * 32 + nt * 8 + 2 * tg;
            if (n < N_TYPE) {
                float b0 = bbias[n];
                out[mrow * N_TYPE + n] = 1.f / (1.f + expf(-(c[mt][nt][0] + b0)));
                out[(mrow + 8) * N_TYPE + n] = 1.f / (1.f + expf(-(c[mt][nt][2] + b0)));
            }
            if (n + 1 < N_TYPE) {
                float b1 = bbias[n + 1];
                out[mrow * N_TYPE + n + 1] = 1.f / (1.f + expf(-(c[mt][nt][1] + b1)));
                out[(mrow + 8) * N_TYPE + n + 1] = 1.f / (1.f + expf(-(c[mt][nt][3] + b1)));
            }
        }
    }
}

// ---------------- launch ----------------
extern "C" void kernel_launch(void* const* d_in, const int* in_sizes, int n_in,
                              void* d_out, int out_size) {
    const int* xb = (const int*)d_in[0];
    const int* ei = (const int*)d_in[1];
    const int* et = (const int*)d_in[2];
    const float* Ew = (const float*)d_in[3];
    const float* Rw = (const float*)d_in[4];
    const float* Tw = (const float*)d_in[5];
    const float* Wf = (const float*)d_in[6];
    const float* av = (const float*)d_in[7];
    const float* cw = (const float*)d_in[8];
    const float* cb = (const float*)d_in[9];
    const float* b1g = (const float*)d_in[10];
    const float* b1b = (const float*)d_in[11];
    const float* b3g = (const float*)d_in[12];
    const float* b3b = (const float*)d_in[13];
    const float* b2g = (const float*)d_in[14];
    const float* b2b = (const float*)d_in[15];
    const float* fcw = (const float*)d_in[16];
    const float* fcb = (const float*)d_in[17];
    const float* bbias = (const float*)d_in[18];
    float* out = (float*)d_out;

    k_zero<<<512, 256>>>();
    k_flag<<<BATCH, NOUT>>>(xb);
    k_compact<<<(N_EDGE + 255) / 256, 256>>>(ei, et);
    k_wa<<<13, 256>>>(Wf, av);
    k_h16<<<N_ENT / 16, 128>>>(Ew, Wf);
    k_rproj<<<N_REL, NOUT>>>(Rw, Wf, av);
    k_score<<<512, 256>>>();
    k_agg<<<1024, 256>>>();
    k_gather<<<BATCH, NOUT>>>(xb);
    k_bn1fin<<<1, 1>>>(b1g, b1b);
    k_conv<<<BATCH, 256>>>(cw, cb);
    k_bn3fin<<<1, 32>>>(b3g, b3b);
    k_prep_fcw<<<(DT * FC_LEN + 255) / 256, 256>>>(fcw);
    {
        dim3 gg(BATCH / 128, 2);
        k_fc<<<gg, 256>>>(fcb);
    }
    k_bn2<<<DT, 128>>>(b2g, b2b);
    k_bn2apply<<<(BATCH * DTP + 255) / 256, 256>>>();
    k_prep_tw<<<(N_TYPE * DTP + 255) / 256, 256>>>(Tw);
    {
        dim3 gg(BATCH / 128, (N_TYPE + 127) / 128);
        k_out<<<gg, 256>>>(bbias, out);
    }
}

// round 9
// speedup vs baseline: 1.0050x; 1.0046x over previous
#include <cuda_runtime.h>
#include <math.h>

#define N_ENT 50000
#define N_REL 237
#define N_TYPE 4000
#define DE 100
#define NOUT 128
#define DT 200
#define DTP 224
#define N_EDGE 800000
#define BATCH 4096
#define NUM_FILT 32
#define CONV_W 60
#define POOL_W 30
#define FC_LEN 960
#define EPS 1e-5f

// ---------------- scratch ----------------
__device__ float g_h[N_ENT * NOUT];
__device__ float g_hd[N_ENT];
__device__ float g_hm[N_ENT];
__device__ float g_wa1[DE];
__device__ float g_wa2[DE];
__device__ float g_rproj[N_REL * NOUT];
__device__ float g_ra[N_REL];
__device__ float g_denom[N_ENT];
__device__ int   g_flag[N_ENT];
__device__ int   g_ecnt;
__device__ int   g_cs[N_EDGE];
__device__ int   g_cd[N_EDGE];
__device__ int   g_ct[N_EDGE];
__device__ float g_ex[N_EDGE];
__device__ float g_agg[N_ENT * NOUT];
__device__ float g_e[BATCH * NOUT];
__device__ float g_conv[BATCH * NUM_FILT * CONV_W];
__device__ float g_y[BATCH * DT];
__device__ float g_z[BATCH * DTP];              // relu(bn2), tf32-rounded, K-padded
__device__ float g_twc[N_TYPE * DTP];           // Tw tf32-rounded, K-padded
__device__ float g_fcwc[DT * FC_LEN];           // fc_w tf32-rounded
__device__ float g_bn1[4];
__device__ float g_bn3sum[NUM_FILT], g_bn3ss[NUM_FILT];
__device__ float g_bn3sc[NUM_FILT], g_bn3sh[NUM_FILT];
__device__ float g_bn2sc[DT], g_bn2sh[DT];

// ---------------- helpers ----------------
__device__ __forceinline__ unsigned f2tf(float x) {
    unsigned r;
    asm("cvt.rna.tf32.f32 %0, %1;" : "=r"(r) : "f"(x));
    return r;
}

__device__ __forceinline__ void mma_tf32(float c[4], const unsigned a[4], const unsigned b[2]) {
    asm volatile(
        "mma.sync.aligned.m16n8k8.row.col.f32.tf32.tf32.f32 "
        "{%0,%1,%2,%3}, {%4,%5,%6,%7}, {%8,%9}, {%0,%1,%2,%3};"
        : "+f"(c[0]), "+f"(c[1]), "+f"(c[2]), "+f"(c[3])
        : "r"(a[0]), "r"(a[1]), "r"(a[2]), "r"(a[3]), "r"(b[0]), "r"(b[1]));
}

// ---------------- small kernels ----------------

__global__ void k_zero() {
    int tid = blockIdx.x * blockDim.x + threadIdx.x;
    int stride = gridDim.x * blockDim.x;
    for (int i = tid; i < N_ENT; i += stride) { g_denom[i] = 0.f; g_flag[i] = 0; }
    if (tid == 0) g_ecnt = 0;
    if (tid < 2) g_bn1[tid] = 0.f;
    for (int i = tid; i < NUM_FILT; i += stride) { g_bn3sum[i] = 0.f; g_bn3ss[i] = 0.f; }
}

__global__ void k_flag(const int* __restrict__ xb) {
    int n = xb[blockIdx.x];
    if (threadIdx.x == 0) g_flag[n] = 1;
    g_agg[n * NOUT + threadIdx.x] = 0.f;
}

// compact edges whose dst is flagged (warp-aggregated atomics)
__global__ void k_compact(const int* __restrict__ ei, const int* __restrict__ et) {
    int e = blockIdx.x * blockDim.x + threadIdx.x;
    int lane = threadIdx.x & 31;
    int dst = -1;
    bool pred = false;
    if (e < N_EDGE) {
        dst = ei[N_EDGE + e];
        pred = (g_flag[dst] != 0);
    }
    unsigned mask = __ballot_sync(0xffffffffu, pred);
    if (mask == 0) return;
    int leader = __ffs(mask) - 1;
    int base = 0;
    if (lane == leader) base = atomicAdd(&g_ecnt, __popc(mask));
    base = __shfl_sync(0xffffffffu, base, leader);
    if (pred) {
        int pos = base + __popc(mask & ((1u << lane) - 1u));
        g_cs[pos] = ei[e];
        g_cd[pos] = dst;
        g_ct[pos] = et[e];
    }
}

// wa1 = W_f @ a1, wa2 = W_f @ a2   (warp per k-row)
__global__ void k_wa(const float* __restrict__ Wf, const float* __restrict__ av) {
    int k = blockIdx.x * 8 + (threadIdx.x >> 5);
    int lane = threadIdx.x & 31;
    if (k >= DE) return;
    float s1 = 0.f, s2 = 0.f;
#pragma unroll
    for (int q = 0; q < 4; q++) {
        int j = lane + q * 32;
        float w = Wf[k * NOUT + j];
        s1 += w * av[j];
        s2 += w * av[NOUT + j];
    }
#pragma unroll
    for (int o = 16; o > 0; o >>= 1) {
        s1 += __shfl_xor_sync(0xffffffffu, s1, o);
        s2 += __shfl_xor_sync(0xffffffffu, s2, o);
    }
    if (lane == 0) { g_hd[k] = 0.f; g_wa1[k] = s1; g_wa2[k] = s2; }
}

// h = Ew @ Wf (16 nodes/block) ; fused hd/hm
__global__ void k_h16(const float* __restrict__ Ew, const float* __restrict__ Wf) {
    int n0 = blockIdx.x * 16;
    int t = threadIdx.x;
    int jl = t & 31;
    int ng = t >> 5;
    __shared__ float er[16][DE];
    for (int i = t; i < 16 * DE; i += 128) er[i / DE][i % DE] = Ew[n0 * DE + i];
    __syncthreads();
    float acc[4][4];
#pragma unroll
    for (int a = 0; a < 4; a++)
#pragma unroll
        for (int b = 0; b < 4; b++) acc[a][b] = 0.f;
    for (int k = 0; k < DE; k++) {
        float w0 = Wf[k * NOUT + jl];
        float w1 = Wf[k * NOUT + jl + 32];
        float w2 = Wf[k * NOUT + jl + 64];
        float w3 = Wf[k * NOUT + jl + 96];
#pragma unroll
        for (int nn = 0; nn < 4; nn++) {
            float e = er[ng * 4 + nn][k];
            acc[nn][0] += e * w0;
            acc[nn][1] += e * w1;
            acc[nn][2] += e * w2;
            acc[nn][3] += e * w3;
        }
    }
#pragma unroll
    for (int nn = 0; nn < 4; nn++)
#pragma unroll
        for (int q = 0; q < 4; q++)
            g_h[(n0 + ng * 4 + nn) * NOUT + q * 32 + jl] = acc[nn][q];
    // fused hd/hm: 8 threads per node
    int oct = t >> 3, ol = t & 7;
    float s1 = 0.f, s2 = 0.f;
    for (int k = ol; k < DE; k += 8) {
        float v = er[oct][k];
        s1 += v * g_wa1[k];
        s2 += v * g_wa2[k];
    }
#pragma unroll
    for (int o = 4; o > 0; o >>= 1) {
        s1 += __shfl_xor_sync(0xffffffffu, s1, o);
        s2 += __shfl_xor_sync(0xffffffffu, s2, o);
    }
    if (ol == 0) { g_hd[n0 + oct] = s1; g_hm[n0 + oct] = s2; }
}

// rproj = R_w @ W_f ; ra = rproj . a2
__global__ void k_rproj(const float* __restrict__ Rw, const float* __restrict__ Wf,
                        const float* __restrict__ av) {
    int r = blockIdx.x, j = threadIdx.x;
    __shared__ float rr[DE];
    __shared__ float red[NOUT];
    if (j < DE) rr[j] = Rw[r * DE + j];
    __syncthreads();
    float acc = 0.f;
#pragma unroll 4
    for (int k = 0; k < DE; k++) acc += rr[k] * Wf[k * NOUT + j];
    g_rproj[r * NOUT + j] = acc;
    red[j] = acc * av[NOUT + j];
    __syncthreads();
    for (int s = 64; s > 0; s >>= 1) {
        if (j < s) red[j] += red[j + s];
        __syncthreads();
    }
    if (j == 0) g_ra[r] = red[0];
}

__global__ void k_score() {
    int tid = blockIdx.x * blockDim.x + threadIdx.x;
    int stride = gridDim.x * blockDim.x;
    int cnt = g_ecnt;
    for (int e = tid; e < cnt; e += stride) {
        int src = g_cs[e], dst = g_cd[e], t = g_ct[e];
        float s = g_hd[dst] + g_hm[src] - g_ra[t];
        s = (s >= 0.f) ? s : 0.2f * s;
        float ex = expf(s);
        g_ex[e] = ex;
        atomicAdd(&g_denom[dst], ex);
    }
}

__global__ void k_agg() {
    int w = (blockIdx.x * blockDim.x + threadIdx.x) >> 5;
    int nwarp = (gridDim.x * blockDim.x) >> 5;
    int lane = threadIdx.x & 31;
    int cnt = g_ecnt;
    for (int e = w; e < cnt; e += nwarp) {
        int src = g_cs[e], dst = g_cd[e], t = g_ct[e];
        float wt = g_ex[e] / (g_denom[dst] + 1e-16f);
        float4 a = reinterpret_cast<const float4*>(&g_h[src * NOUT])[lane];
        float4 b = reinterpret_cast<const float4*>(&g_rproj[t * NOUT])[lane];
        float4 v;
        v.x = wt * (a.x - b.x); v.y = wt * (a.y - b.y);
        v.z = wt * (a.z - b.z); v.w = wt * (a.w - b.w);
        float* p = &g_agg[dst * NOUT + lane * 4];
        asm volatile("red.global.add.v4.f32 [%0], {%1,%2,%3,%4};"
                     :: "l"(p), "f"(v.x), "f"(v.y), "f"(v.z), "f"(v.w) : "memory");
    }
}

__global__ void k_gather(const int* __restrict__ xb) {
    int b = blockIdx.x, j = threadIdx.x;
    __shared__ float r1[NOUT], r2[NOUT];
    float v = g_agg[xb[b] * NOUT + j];
    float e = (v > 0.f) ? v : expm1f(v);
    g_e[b * NOUT + j] = e;
    r1[j] = e;
    r2[j] = e * e;
    __syncthreads();
    for (int s = 64; s > 0; s >>= 1) {
        if (j < s) { r1[j] += r1[j + s]; r2[j] += r2[j + s]; }
        __syncthreads();
    }
    if (j == 0) { atomicAdd(&g_bn1[0], r1[0]); atomicAdd(&g_bn1[1], r2[0]); }
}

__global__ void k_bn1fin(const float* __restrict__ g, const float* __restrict__ b) {
    float cnt = (float)(BATCH * NOUT);
    float mean = g_bn1[0] / cnt;
    float var = g_bn1[1] / cnt - mean * mean;
    float inv = rsqrtf(var + EPS);
    float sc = g[0] * inv;
    g_bn1[2] = sc;
    g_bn1[3] = b[0] - sc * mean;
}

__global__ void k_conv(const float* __restrict__ cw, const float* __restrict__ cb) {
    int b = blockIdx.x, tid = threadIdx.x;
    __shared__ float es[NOUT];
    __shared__ float wsm[NUM_FILT * 9];
    __shared__ float co[NUM_FILT * CONV_W];
    float sc = g_bn1[2], sh = g_bn1[3];
    if (tid < NOUT) es[tid] = sc * g_e[b * NOUT + tid] + sh;
    for (int i = tid; i < NUM_FILT * 9; i += blockDim.x) wsm[i] = cw[i];
    __syncthreads();
    for (int i = tid; i < NUM_FILT * CONV_W; i += blockDim.x) {
        int c = i / CONV_W, w = i % CONV_W;
        float acc = cb[c];
#pragma unroll
        for (int k = 0; k < 9; k++) acc += wsm[c * 9 + k] * es[2 * w + k];
        co[i] = acc;
        g_conv[b * NUM_FILT * CONV_W + i] = acc;
    }
    __syncthreads();
    if (tid < NUM_FILT) {
        float s = 0.f, ss = 0.f;
        for (int w = 0; w < CONV_W; w++) {
            float v = co[tid * CONV_W + w];
            s += v; ss += v * v;
        }
        atomicAdd(&g_bn3sum[tid], s);
        atomicAdd(&g_bn3ss[tid], ss);
    }
}

__global__ void k_bn3fin(const float* __restrict__ g, const float* __restrict__ b) {
    int c = threadIdx.x;
    if (c >= NUM_FILT) return;
    float cnt = (float)(BATCH * CONV_W);
    float mean = g_bn3sum[c] / cnt;
    float var = g_bn3ss[c] / cnt - mean * mean;
    float inv = rsqrtf(var + EPS);
    float sc = g[c] * inv;
    g_bn3sc[c] = sc;
    g_bn3sh[c] = b[c] - sc * mean;
}

// prep: convert weights to tf32-rounded copies (padded K for Tw)
__global__ void k_prep_tw(const float* __restrict__ Tw) {
    int i = blockIdx.x * blockDim.x + threadIdx.x;
    if (i >= N_TYPE * DTP) return;
    int n = i / DTP, k = i % DTP;
    float v = (k < DT) ? Tw[n * DT + k] : 0.f;
    g_twc[i] = __uint_as_float(f2tf(v));
}

__global__ void k_prep_fcw(const float* __restrict__ fcw) {
    int i = blockIdx.x * blockDim.x + threadIdx.x;
    if (i >= DT * FC_LEN) return;
    g_fcwc[i] = __uint_as_float(f2tf(fcw[i]));
}

// ---------------- tf32 GEMM 1: fc  y[4096,200] = F[4096,960] @ fcw^T ----------------
// F built on the fly: bn3 + relu + maxpool over g_conv.
#define SAP 36
__global__ void __launch_bounds__(256) k_fc(const float* __restrict__ fcb) {
    __shared__ unsigned As[128 * SAP];
    __shared__ unsigned Bs[128 * SAP];
    int t = threadIdx.x;
    int warp = t >> 5, lane = t & 31;
    int wm = warp >> 2, wn = warp & 3;      // 2 x 4 warps
    int g = lane >> 2, tg = lane & 3;
    int m0 = blockIdx.x * 128;
    int n0 = blockIdx.y * 128;
    int lrow = t >> 1, lpart = (t & 1) * 16;

    float c[4][4][4];
#pragma unroll
    for (int i = 0; i < 4; i++)
#pragma unroll
        for (int j = 0; j < 4; j++)
#pragma unroll
            for (int q = 0; q < 4; q++) c[i][j][q] = 0.f;

    for (int kc = 0; kc < FC_LEN / 32; kc++) {
        int k0g = kc * 32;
        // stage A: pooled+bn3+relu features, tf32-rounded
        {
            int b = m0 + lrow;
            const float* crow = &g_conv[b * (NUM_FILT * CONV_W)];
#pragma unroll
            for (int q = 0; q < 16; q++) {
                int kk = k0g + lpart + q;
                int ch = kk / POOL_W, w = kk % POOL_W;
                float sc = g_bn3sc[ch], sh = g_bn3sh[ch];
                float x0 = crow[ch * CONV_W + 2 * w];
                float x1 = crow[ch * CONV_W + 2 * w + 1];
                float v = fmaxf(fmaxf(sc * x0 + sh, sc * x1 + sh), 0.f);
                As[lrow * SAP + lpart + q] = f2tf(v);
            }
        }
        // stage B: fcw rows (guard n<200)
        {
            int n = n0 + lrow;
            if (n < DT) {
                const float4* src = reinterpret_cast<const float4*>(&g_fcwc[n * FC_LEN + k0g + lpart]);
#pragma unroll
                for (int q = 0; q < 4; q++) {
                    float4 v = src[q];
                    Bs[lrow * SAP + lpart + q * 4 + 0] = __float_as_uint(v.x);
                    Bs[lrow * SAP + lpart + q * 4 + 1] = __float_as_uint(v.y);
                    Bs[lrow * SAP + lpart + q * 4 + 2] = __float_as_uint(v.z);
                    Bs[lrow * SAP + lpart + q * 4 + 3] = __float_as_uint(v.w);
                }
            } else {
#pragma unroll
                for (int q = 0; q < 16; q++) Bs[lrow * SAP + lpart + q] = 0u;
            }
        }
        __syncthreads();
#pragma unroll
        for (int kk = 0; kk < 4; kk++) {
            int k0 = kk * 8;
            unsigned ar[4][4], br[4][2];
#pragma unroll
            for (int mt = 0; mt < 4; mt++) {
                int r = wm * 64 + mt * 16 + g;
                ar[mt][0] = As[r * SAP + k0 + tg];
                ar[mt][1] = As[(r + 8) * SAP + k0 + tg];
                ar[mt][2] = As[r * SAP + k0 + tg + 4];
                ar[mt][3] = As[(r + 8) * SAP + k0 + tg + 4];
            }
#pragma unroll
            for (int nt = 0; nt < 4; nt++) {
                int r = wn * 32 + nt * 8 + g;
                br[nt][0] = Bs[r * SAP + k0 + tg];
                br[nt][1] = Bs[r * SAP + k0 + tg + 4];
            }
#pragma unroll
            for (int mt = 0; mt < 4; mt++)
#pragma unroll
                for (int nt = 0; nt < 4; nt++) mma_tf32(c[mt][nt], ar[mt], br[nt]);
        }
        __syncthreads();
    }
    // epilogue: y = c + fcb
#pragma unroll
    for (int mt = 0; mt < 4; mt++) {
        int mrow = m0 + wm * 64 + mt * 16 + g;
#pragma unroll
        for (int nt = 0; nt < 4; nt++) {
            int n = n0 + wn * 32 + nt * 8 + 2 * tg;
            if (n < DT)     g_y[mrow * DT + n]           = c[mt][nt][0] + fcb[n];
            if (n + 1 < DT) g_y[mrow * DT + n + 1]       = c[mt][nt][1] + fcb[n + 1];
            if (n < DT)     g_y[(mrow + 8) * DT + n]     = c[mt][nt][2] + fcb[n];
            if (n + 1 < DT) g_y[(mrow + 8) * DT + n + 1] = c[mt][nt][3] + fcb[n + 1];
        }
    }
}

// bn2 stats + finalize: one block per feature column
__global__ void k_bn2(const float* __restrict__ g, const float* __restrict__ b) {
    int k = blockIdx.x, tid = threadIdx.x;
    __shared__ float r1[128], r2[128];
    float s = 0.f, ss = 0.f;
    for (int i = tid; i < BATCH; i += 128) {
        float v = g_y[i * DT + k];
        s += v; ss += v * v;
    }
    r1[tid] = s; r2[tid] = ss;
    __syncthreads();
    for (int o = 64; o > 0; o >>= 1) {
        if (tid < o) { r1[tid] += r1[tid + o]; r2[tid] += r2[tid + o]; }
        __syncthreads();
    }
    if (tid == 0) {
        float cnt = (float)BATCH;
        float mean = r1[0] / cnt;
        float var = r2[0] / cnt - mean * mean;
        float inv = rsqrtf(var + EPS);
        float sc = g[k] * inv;
        g_bn2sc[k] = sc;
        g_bn2sh[k] = b[k] - sc * mean;
    }
}

// z = relu(bn2(y)), tf32-rounded, zero-padded to DTP
__global__ void k_bn2apply() {
    int i = blockIdx.x * blockDim.x + threadIdx.x;
    if (i >= BATCH * DTP) return;
    int k = i % DTP;
    float v = 0.f;
    if (k < DT) v = fmaxf(g_bn2sc[k] * g_y[(i / DTP) * DT + k] + g_bn2sh[k], 0.f);
    g_z[i] = __uint_as_float(f2tf(v));
}

// ---------------- tf32 GEMM 2: out = sigmoid(Z @ Tw^T + bias) ----------------
__global__ void __launch_bounds__(256) k_out(const float* __restrict__ bbias,
                                             float* __restrict__ out) {
    __shared__ unsigned As[128 * SAP];
    __shared__ unsigned Bs[128 * SAP];
    int t = threadIdx.x;
    int warp = t >> 5, lane = t & 31;
    int wm = warp >> 2, wn = warp & 3;
    int g = lane >> 2, tg = lane & 3;
    int m0 = blockIdx.x * 128;
    int n0 = blockIdx.y * 128;
    int lrow = t >> 1, lpart = (t & 1) * 16;

    float c[4][4][4];
#pragma unroll
    for (int i = 0; i < 4; i++)
#pragma unroll
        for (int j = 0; j < 4; j++)
#pragma unroll
            for (int q = 0; q < 4; q++) c[i][j][q] = 0.f;

    for (int kc = 0; kc < DTP / 32; kc++) {
        int k0g = kc * 32;
        {
            const float4* src = reinterpret_cast<const float4*>(&g_z[(m0 + lrow) * DTP + k0g + lpart]);
#pragma unroll
            for (int q = 0; q < 4; q++) {
                float4 v = src[q];
                As[lrow * SAP + lpart + q * 4 + 0] = __float_as_uint(v.x);
                As[lrow * SAP + lpart + q * 4 + 1] = __float_as_uint(v.y);
                As[lrow * SAP + lpart + q * 4 + 2] = __float_as_uint(v.z);
                As[lrow * SAP + lpart + q * 4 + 3] = __float_as_uint(v.w);
            }
        }
        {
            int n = n0 + lrow;
            if (n < N_TYPE) {
                const float4* src = reinterpret_cast<const float4*>(&g_twc[n * DTP + k0g + lpart]);
#pragma unroll
                for (int q = 0; q < 4; q++) {
                    float4 v = src[q];
                    Bs[lrow * SAP + lpart + q * 4 + 0] = __float_as_uint(v.x);
                    Bs[lrow * SAP + lpart + q * 4 + 1] = __float_as_uint(v.y);
                    Bs[lrow * SAP + lpart + q * 4 + 2] = __float_as_uint(v.z);
                    Bs[lrow * SAP + lpart + q * 4 + 3] = __float_as_uint(v.w);
                }
            } else {
#pragma unroll
                for (int q = 0; q < 16; q++) Bs[lrow * SAP + lpart + q] = 0u;
            }
        }
        __syncthreads();
#pragma unroll
        for (int kk = 0; kk < 4; kk++) {
            int k0 = kk * 8;
            unsigned ar[4][4], br[4][2];
#pragma unroll
            for (int mt = 0; mt < 4; mt++) {
                int r = wm * 64 + mt * 16 + g;
                ar[mt][0] = As[r * SAP + k0 + tg];
                ar[mt][1] = As[(r + 8) * SAP + k0 + tg];
                ar[mt][2] = As[r * SAP + k0 + tg + 4];
                ar[mt][3] = As[(r + 8) * SAP + k0 + tg + 4];
            }
#pragma unroll
            for (int nt = 0; nt < 4; nt++) {
                int r = wn * 32 + nt * 8 + g;
                br[nt][0] = Bs[r * SAP + k0 + tg];
                br[nt][1] = Bs[r * SAP + k0 + tg + 4];
            }
#pragma unroll
            for (int mt = 0; mt < 4; mt++)
#pragma unroll
                for (int nt = 0; nt < 4; nt++) mma_tf32(c[mt][nt], ar[mt], br[nt]);
        }
        __syncthreads();
    }
#pragma unroll
    for (int mt = 0; mt < 4; mt++) {
        int mrow = m0 + wm * 64 + mt * 16 + g;
#pragma unroll
        for (int nt = 0; nt < 4; nt++) {
            int n = n0 + wn * 32 + nt * 8 + 2 * tg;
            if (n < N_TYPE) {
                float b0 = bbias[n];
                out[mrow * N_TYPE + n] = 1.f / (1.f + expf(-(c[mt][nt][0] + b0)));
                out[(mrow + 8) * N_TYPE + n] = 1.f / (1.f + expf(-(c[mt][nt][2] + b0)));
            }
            if (n + 1 < N_TYPE) {
                float b1 = bbias[n + 1];
                out[mrow * N_TYPE + n + 1] = 1.f / (1.f + expf(-(c[mt][nt][1] + b1)));
                out[(mrow + 8) * N_TYPE + n + 1] = 1.f / (1.f + expf(-(c[mt][nt][3] + b1)));
            }
        }
    }
}

// ---------------- launch ----------------
extern "C" void kernel_launch(void* const* d_in, const int* in_sizes, int n_in,
                              void* d_out, int out_size) {
    const int* xb = (const int*)d_in[0];
    const int* ei = (const int*)d_in[1];
    const int* et = (const int*)d_in[2];
    const float* Ew = (const float*)d_in[3];
    const float* Rw = (const float*)d_in[4];
    const float* Tw = (const float*)d_in[5];
    const float* Wf = (const float*)d_in[6];
    const float* av = (const float*)d_in[7];
    const float* cw = (const float*)d_in[8];
    const float* cb = (const float*)d_in[9];
    const float* b1g = (const float*)d_in[10];
    const float* b1b = (const float*)d_in[11];
    const float* b3g = (const float*)d_in[12];
    const float* b3b = (const float*)d_in[13];
    const float* b2g = (const float*)d_in[14];
    const float* b2b = (const float*)d_in[15];
    const float* fcw = (const float*)d_in[16];
    const float* fcb = (const float*)d_in[17];
    const float* bbias = (const float*)d_in[18];
    float* out = (float*)d_out;

    k_zero<<<512, 256>>>();
    k_flag<<<BATCH, NOUT>>>(xb);
    k_compact<<<(N_EDGE + 255) / 256, 256>>>(ei, et);
    k_wa<<<13, 256>>>(Wf, av);
    k_h16<<<N_ENT / 16, 128>>>(Ew, Wf);
    k_rproj<<<N_REL, NOUT>>>(Rw, Wf, av);
    k_score<<<512, 256>>>();
    k_agg<<<1024, 256>>>();
    k_gather<<<BATCH, NOUT>>>(xb);
    k_bn1fin<<<1, 1>>>(b1g, b1b);
    k_conv<<<BATCH, 256>>>(cw, cb);
    k_bn3fin<<<1, 32>>>(b3g, b3b);
    k_prep_fcw<<<(DT * FC_LEN + 255) / 256, 256>>>(fcw);
    {
        dim3 gg(BATCH / 128, 2);
        k_fc<<<gg, 256>>>(fcb);
    }
    k_bn2<<<DT, 128>>>(b2g, b2b);
    k_bn2apply<<<(BATCH * DTP + 255) / 256, 256>>>();
    k_prep_tw<<<(N_TYPE * DTP + 255) / 256, 256>>>(Tw);
    {
        dim3 gg(BATCH / 128, (N_TYPE + 127) / 128);
        k_out<<<gg, 256>>>(bbias, out);
    }
}

// round 10
// speedup vs baseline: 1.0057x; 1.0007x over previous
#include <cuda_runtime.h>
#include <math.h>

#define N_ENT 50000
#define N_REL 237
#define N_TYPE 4000
#define DE 100
#define NOUT 128
#define DT 200
#define DTP 224
#define N_EDGE 800000
#define BATCH 4096
#define NUM_FILT 32
#define CONV_W 60
#define POOL_W 30
#define FC_LEN 960
#define EPS 1e-5f

// ---------------- scratch ----------------
__device__ float g_h[N_ENT * NOUT];
__device__ float g_hd[N_ENT];
__device__ float g_hm[N_ENT];
__device__ float g_wa1[DE];
__device__ float g_wa2[DE];
__device__ float g_rproj[N_REL * NOUT];
__device__ float g_ra[N_REL];
__device__ float g_denom[N_ENT];
__device__ int   g_flag[N_ENT];
__device__ int   g_ecnt;
__device__ int   g_cs[N_EDGE];
__device__ int   g_cd[N_EDGE];
__device__ int   g_ct[N_EDGE];
__device__ float g_ex[N_EDGE];
__device__ float g_agg[N_ENT * NOUT];
__device__ float g_e[BATCH * NOUT];
__device__ float g_conv[BATCH * NUM_FILT * CONV_W];
__device__ float g_y[BATCH * DT];
__device__ float g_z[BATCH * DTP];              // relu(bn2), tf32-rounded, K-padded
__device__ float g_twc[N_TYPE * DTP];           // Tw tf32-rounded, K-padded
__device__ float g_fcwc[DT * FC_LEN];           // fc_w tf32-rounded
__device__ float g_bn1[4];
__device__ float g_bn3sum[NUM_FILT], g_bn3ss[NUM_FILT];
__device__ float g_bn3sc[NUM_FILT], g_bn3sh[NUM_FILT];
__device__ float g_bn2sc[DT], g_bn2sh[DT];

// ---------------- helpers ----------------
__device__ __forceinline__ unsigned f2tf(float x) {
    unsigned r;
    asm("cvt.rna.tf32.f32 %0, %1;" : "=r"(r) : "f"(x));
    return r;
}

__device__ __forceinline__ void mma_tf32(float c[4], const unsigned a[4], const unsigned b[2]) {
    asm volatile(
        "mma.sync.aligned.m16n8k8.row.col.f32.tf32.tf32.f32 "
        "{%0,%1,%2,%3}, {%4,%5,%6,%7}, {%8,%9}, {%0,%1,%2,%3};"
        : "+f"(c[0]), "+f"(c[1]), "+f"(c[2]), "+f"(c[3])
        : "r"(a[0]), "r"(a[1]), "r"(a[2]), "r"(a[3]), "r"(b[0]), "r"(b[1]));
}

// ---------------- small kernels ----------------

__global__ void k_zero() {
    int tid = blockIdx.x * blockDim.x + threadIdx.x;
    int stride = gridDim.x * blockDim.x;
    for (int i = tid; i < N_ENT; i += stride) { g_denom[i] = 0.f; g_flag[i] = 0; }
    if (tid == 0) g_ecnt = 0;
    if (tid < 2) g_bn1[tid] = 0.f;
    for (int i = tid; i < NUM_FILT; i += stride) { g_bn3sum[i] = 0.f; g_bn3ss[i] = 0.f; }
}

__global__ void k_flag(const int* __restrict__ xb) {
    int n = xb[blockIdx.x];
    if (threadIdx.x == 0) g_flag[n] = 1;
    g_agg[n * NOUT + threadIdx.x] = 0.f;
}

// compact edges whose dst is flagged (warp-aggregated atomics)
__global__ void k_compact(const int* __restrict__ ei, const int* __restrict__ et) {
    int e = blockIdx.x * blockDim.x + threadIdx.x;
    int lane = threadIdx.x & 31;
    int dst = -1;
    bool pred = false;
    if (e < N_EDGE) {
        dst = ei[N_EDGE + e];
        pred = (g_flag[dst] != 0);
    }
    unsigned mask = __ballot_sync(0xffffffffu, pred);
    if (mask == 0) return;
    int leader = __ffs(mask) - 1;
    int base = 0;
    if (lane == leader) base = atomicAdd(&g_ecnt, __popc(mask));
    base = __shfl_sync(0xffffffffu, base, leader);
    if (pred) {
        int pos = base + __popc(mask & ((1u << lane) - 1u));
        g_cs[pos] = ei[e];
        g_cd[pos] = dst;
        g_ct[pos] = et[e];
    }
}

// wa1 = W_f @ a1, wa2 = W_f @ a2   (warp per k-row)
__global__ void k_wa(const float* __restrict__ Wf, const float* __restrict__ av) {
    int k = blockIdx.x * 8 + (threadIdx.x >> 5);
    int lane = threadIdx.x & 31;
    if (k >= DE) return;
    float s1 = 0.f, s2 = 0.f;
#pragma unroll
    for (int q = 0; q < 4; q++) {
        int j = lane + q * 32;
        float w = Wf[k * NOUT + j];
        s1 += w * av[j];
        s2 += w * av[NOUT + j];
    }
#pragma unroll
    for (int o = 16; o > 0; o >>= 1) {
        s1 += __shfl_xor_sync(0xffffffffu, s1, o);
        s2 += __shfl_xor_sync(0xffffffffu, s2, o);
    }
    if (lane == 0) { g_hd[k] = 0.f; g_wa1[k] = s1; g_wa2[k] = s2; }
}

// h = Ew @ Wf (16 nodes/block) ; fused hd/hm
__global__ void k_h16(const float* __restrict__ Ew, const float* __restrict__ Wf) {
    int n0 = blockIdx.x * 16;
    int t = threadIdx.x;
    int jl = t & 31;
    int ng = t >> 5;
    __shared__ float er[16][DE];
    for (int i = t; i < 16 * DE; i += 128) er[i / DE][i % DE] = Ew[n0 * DE + i];
    __syncthreads();
    float acc[4][4];
#pragma unroll
    for (int a = 0; a < 4; a++)
#pragma unroll
        for (int b = 0; b < 4; b++) acc[a][b] = 0.f;
    for (int k = 0; k < DE; k++) {
        float w0 = Wf[k * NOUT + jl];
        float w1 = Wf[k * NOUT + jl + 32];
        float w2 = Wf[k * NOUT + jl + 64];
        float w3 = Wf[k * NOUT + jl + 96];
#pragma unroll
        for (int nn = 0; nn < 4; nn++) {
            float e = er[ng * 4 + nn][k];
            acc[nn][0] += e * w0;
            acc[nn][1] += e * w1;
            acc[nn][2] += e * w2;
            acc[nn][3] += e * w3;
        }
    }
#pragma unroll
    for (int nn = 0; nn < 4; nn++)
#pragma unroll
        for (int q = 0; q < 4; q++)
            g_h[(n0 + ng * 4 + nn) * NOUT + q * 32 + jl] = acc[nn][q];
    // fused hd/hm: 8 threads per node
    int oct = t >> 3, ol = t & 7;
    float s1 = 0.f, s2 = 0.f;
    for (int k = ol; k < DE; k += 8) {
        float v = er[oct][k];
        s1 += v * g_wa1[k];
        s2 += v * g_wa2[k];
    }
#pragma unroll
    for (int o = 4; o > 0; o >>= 1) {
        s1 += __shfl_xor_sync(0xffffffffu, s1, o);
        s2 += __shfl_xor_sync(0xffffffffu, s2, o);
    }
    if (ol == 0) { g_hd[n0 + oct] = s1; g_hm[n0 + oct] = s2; }
}

// rproj = R_w @ W_f ; ra = rproj . a2
__global__ void k_rproj(const float* __restrict__ Rw, const float* __restrict__ Wf,
                        const float* __restrict__ av) {
    int r = blockIdx.x, j = threadIdx.x;
    __shared__ float rr[DE];
    __shared__ float red[NOUT];
    if (j < DE) rr[j] = Rw[r * DE + j];
    __syncthreads();
    float acc = 0.f;
#pragma unroll 4
    for (int k = 0; k < DE; k++) acc += rr[k] * Wf[k * NOUT + j];
    g_rproj[r * NOUT + j] = acc;
    red[j] = acc * av[NOUT + j];
    __syncthreads();
    for (int s = 64; s > 0; s >>= 1) {
        if (j < s) red[j] += red[j + s];
        __syncthreads();
    }
    if (j == 0) g_ra[r] = red[0];
}

__global__ void k_score() {
    int tid = blockIdx.x * blockDim.x + threadIdx.x;
    int stride = gridDim.x * blockDim.x;
    int cnt = g_ecnt;
    for (int e = tid; e < cnt; e += stride) {
        int src = g_cs[e], dst = g_cd[e], t = g_ct[e];
        float s = g_hd[dst] + g_hm[src] - g_ra[t];
        s = (s >= 0.f) ? s : 0.2f * s;
        float ex = expf(s);
        g_ex[e] = ex;
        atomicAdd(&g_denom[dst], ex);
    }
}

__global__ void k_agg() {
    int w = (blockIdx.x * blockDim.x + threadIdx.x) >> 5;
    int nwarp = (gridDim.x * blockDim.x) >> 5;
    int lane = threadIdx.x & 31;
    int cnt = g_ecnt;
    for (int e = w; e < cnt; e += nwarp) {
        int src = g_cs[e], dst = g_cd[e], t = g_ct[e];
        float wt = g_ex[e] / (g_denom[dst] + 1e-16f);
        float4 a = reinterpret_cast<const float4*>(&g_h[src * NOUT])[lane];
        float4 b = reinterpret_cast<const float4*>(&g_rproj[t * NOUT])[lane];
        float4 v;
        v.x = wt * (a.x - b.x); v.y = wt * (a.y - b.y);
        v.z = wt * (a.z - b.z); v.w = wt * (a.w - b.w);
        float* p = &g_agg[dst * NOUT + lane * 4];
        asm volatile("red.global.add.v4.f32 [%0], {%1,%2,%3,%4};"
                     :: "l"(p), "f"(v.x), "f"(v.y), "f"(v.z), "f"(v.w) : "memory");
    }
}

__global__ void k_gather(const int* __restrict__ xb) {
    int b = blockIdx.x, j = threadIdx.x;
    __shared__ float r1[NOUT], r2[NOUT];
    float v = g_agg[xb[b] * NOUT + j];
    float e = (v > 0.f) ? v : expm1f(v);
    g_e[b * NOUT + j] = e;
    r1[j] = e;
    r2[j] = e * e;
    __syncthreads();
    for (int s = 64; s > 0; s >>= 1) {
        if (j < s) { r1[j] += r1[j + s]; r2[j] += r2[j + s]; }
        __syncthreads();
    }
    if (j == 0) { atomicAdd(&g_bn1[0], r1[0]); atomicAdd(&g_bn1[1], r2[0]); }
}

__global__ void k_bn1fin(const float* __restrict__ g, const float* __restrict__ b) {
    float cnt = (float)(BATCH * NOUT);
    float mean = g_bn1[0] / cnt;
    float var = g_bn1[1] / cnt - mean * mean;
    float inv = rsqrtf(var + EPS);
    float sc = g[0] * inv;
    g_bn1[2] = sc;
    g_bn1[3] = b[0] - sc * mean;
}

__global__ void k_conv(const float* __restrict__ cw, const float* __restrict__ cb) {
    int b = blockIdx.x, tid = threadIdx.x;
    __shared__ float es[NOUT];
    __shared__ float wsm[NUM_FILT * 9];
    __shared__ float co[NUM_FILT * CONV_W];
    float sc = g_bn1[2], sh = g_bn1[3];
    if (tid < NOUT) es[tid] = sc * g_e[b * NOUT + tid] + sh;
    for (int i = tid; i < NUM_FILT * 9; i += blockDim.x) wsm[i] = cw[i];
    __syncthreads();
    for (int i = tid; i < NUM_FILT * CONV_W; i += blockDim.x) {
        int c = i / CONV_W, w = i % CONV_W;
        float acc = cb[c];
#pragma unroll
        for (int k = 0; k < 9; k++) acc += wsm[c * 9 + k] * es[2 * w + k];
        co[i] = acc;
        g_conv[b * NUM_FILT * CONV_W + i] = acc;
    }
    __syncthreads();
    if (tid < NUM_FILT) {
        float s = 0.f, ss = 0.f;
        for (int w = 0; w < CONV_W; w++) {
            float v = co[tid * CONV_W + w];
            s += v; ss += v * v;
        }
        atomicAdd(&g_bn3sum[tid], s);
        atomicAdd(&g_bn3ss[tid], ss);
    }
}

__global__ void k_bn3fin(const float* __restrict__ g, const float* __restrict__ b) {
    int c = threadIdx.x;
    if (c >= NUM_FILT) return;
    float cnt = (float)(BATCH * CONV_W);
    float mean = g_bn3sum[c] / cnt;
    float var = g_bn3ss[c] / cnt - mean * mean;
    float inv = rsqrtf(var + EPS);
    float sc = g[c] * inv;
    g_bn3sc[c] = sc;
    g_bn3sh[c] = b[c] - sc * mean;
}

// prep: convert weights to tf32-rounded copies (padded K for Tw)
__global__ void k_prep_tw(const float* __restrict__ Tw) {
    int i = blockIdx.x * blockDim.x + threadIdx.x;
    if (i >= N_TYPE * DTP) return;
    int n = i / DTP, k = i % DTP;
    float v = (k < DT) ? Tw[n * DT + k] : 0.f;
    g_twc[i] = __uint_as_float(f2tf(v));
}

__global__ void k_prep_fcw(const float* __restrict__ fcw) {
    int i = blockIdx.x * blockDim.x + threadIdx.x;
    if (i >= DT * FC_LEN) return;
    g_fcwc[i] = __uint_as_float(f2tf(fcw[i]));
}

// ---------------- tf32 GEMM 1: fc  y[4096,200] = F[4096,960] @ fcw^T ----------------
// F built on the fly: bn3 + relu + maxpool over g_conv.
#define SAP 36
__global__ void __launch_bounds__(256) k_fc(const float* __restrict__ fcb) {
    __shared__ unsigned As[128 * SAP];
    __shared__ unsigned Bs[128 * SAP];
    int t = threadIdx.x;
    int warp = t >> 5, lane = t & 31;
    int wm = warp >> 2, wn = warp & 3;      // 2 x 4 warps
    int g = lane >> 2, tg = lane & 3;
    int m0 = blockIdx.x * 128;
    int n0 = blockIdx.y * 128;
    int lrow = t >> 1, lpart = (t & 1) * 16;

    float c[4][4][4];
#pragma unroll
    for (int i = 0; i < 4; i++)
#pragma unroll
        for (int j = 0; j < 4; j++)
#pragma unroll
            for (int q = 0; q < 4; q++) c[i][j][q] = 0.f;

    for (int kc = 0; kc < FC_LEN / 32; kc++) {
        int k0g = kc * 32;
        // stage A: pooled+bn3+relu features, tf32-rounded
        {
            int b = m0 + lrow;
            const float* crow = &g_conv[b * (NUM_FILT * CONV_W)];
#pragma unroll
            for (int q = 0; q < 16; q++) {
                int kk = k0g + lpart + q;
                int ch = kk / POOL_W, w = kk % POOL_W;
                float sc = g_bn3sc[ch], sh = g_bn3sh[ch];
                float x0 = crow[ch * CONV_W + 2 * w];
                float x1 = crow[ch * CONV_W + 2 * w + 1];
                float v = fmaxf(fmaxf(sc * x0 + sh, sc * x1 + sh), 0.f);
                As[lrow * SAP + lpart + q] = f2tf(v);
            }
        }
        // stage B: fcw rows (guard n<200)
        {
            int n = n0 + lrow;
            if (n < DT) {
                const float4* src = reinterpret_cast<const float4*>(&g_fcwc[n * FC_LEN + k0g + lpart]);
#pragma unroll
                for (int q = 0; q < 4; q++) {
                    float4 v = src[q];
                    Bs[lrow * SAP + lpart + q * 4 + 0] = __float_as_uint(v.x);
                    Bs[lrow * SAP + lpart + q * 4 + 1] = __float_as_uint(v.y);
                    Bs[lrow * SAP + lpart + q * 4 + 2] = __float_as_uint(v.z);
                    Bs[lrow * SAP + lpart + q * 4 + 3] = __float_as_uint(v.w);
                }
            } else {
#pragma unroll
                for (int q = 0; q < 16; q++) Bs[lrow * SAP + lpart + q] = 0u;
            }
        }
        __syncthreads();
#pragma unroll
        for (int kk = 0; kk < 4; kk++) {
            int k0 = kk * 8;
            unsigned ar[4][4], br[4][2];
#pragma unroll
            for (int mt = 0; mt < 4; mt++) {
                int r = wm * 64 + mt * 16 + g;
                ar[mt][0] = As[r * SAP + k0 + tg];
                ar[mt][1] = As[(r + 8) * SAP + k0 + tg];
                ar[mt][2] = As[r * SAP + k0 + tg + 4];
                ar[mt][3] = As[(r + 8) * SAP + k0 + tg + 4];
            }
#pragma unroll
            for (int nt = 0; nt < 4; nt++) {
                int r = wn * 32 + nt * 8 + g;
                br[nt][0] = Bs[r * SAP + k0 + tg];
                br[nt][1] = Bs[r * SAP + k0 + tg + 4];
            }
#pragma unroll
            for (int mt = 0; mt < 4; mt++)
#pragma unroll
                for (int nt = 0; nt < 4; nt++) mma_tf32(c[mt][nt], ar[mt], br[nt]);
        }
        __syncthreads();
    }
    // epilogue: y = c + fcb
#pragma unroll
    for (int mt = 0; mt < 4; mt++) {
        int mrow = m0 + wm * 64 + mt * 16 + g;
#pragma unroll
        for (int nt = 0; nt < 4; nt++) {
            int n = n0 + wn * 32 + nt * 8 + 2 * tg;
            if (n < DT)     g_y[mrow * DT + n]           = c[mt][nt][0] + fcb[n];
            if (n + 1 < DT) g_y[mrow * DT + n + 1]       = c[mt][nt][1] + fcb[n + 1];
            if (n < DT)     g_y[(mrow + 8) * DT + n]     = c[mt][nt][2] + fcb[n];
            if (n + 1 < DT) g_y[(mrow + 8) * DT + n + 1] = c[mt][nt][3] + fcb[n + 1];
        }
    }
}

// bn2 stats + finalize: one block per feature column
__global__ void k_bn2(const float* __restrict__ g, const float* __restrict__ b) {
    int k = blockIdx.x, tid = threadIdx.x;
    __shared__ float r1[128], r2[128];
    float s = 0.f, ss = 0.f;
    for (int i = tid; i < BATCH; i += 128) {
        float v = g_y[i * DT + k];
        s += v; ss += v * v;
    }
    r1[tid] = s; r2[tid] = ss;
    __syncthreads();
    for (int o = 64; o > 0; o >>= 1) {
        if (tid < o) { r1[tid] += r1[tid + o]; r2[tid] += r2[tid + o]; }
        __syncthreads();
    }
    if (tid == 0) {
        float cnt = (float)BATCH;
        float mean = r1[0] / cnt;
        float var = r2[0] / cnt - mean * mean;
        float inv = rsqrtf(var + EPS);
        float sc = g[k] * inv;
        g_bn2sc[k] = sc;
        g_bn2sh[k] = b[k] - sc * mean;
    }
}

// z = relu(bn2(y)), tf32-rounded, zero-padded to DTP
__global__ void k_bn2apply() {
    int i = blockIdx.x * blockDim.x + threadIdx.x;
    if (i >= BATCH * DTP) return;
    int k = i % DTP;
    float v = 0.f;
    if (k < DT) v = fmaxf(g_bn2sc[k] * g_y[(i / DTP) * DT + k] + g_bn2sh[k], 0.f);
    g_z[i] = __uint_as_float(f2tf(v));
}

// ---------------- tf32 GEMM 2: out = sigmoid(Z @ Tw^T + bias) ----------------
__global__ void __launch_bounds__(256) k_out(const float* __restrict__ bbias,
                                             float* __restrict__ out) {
    __shared__ unsigned As[128 * SAP];
    __shared__ unsigned Bs[128 * SAP];
    int t = threadIdx.x;
    int warp = t >> 5, lane = t & 31;
    int wm = warp >> 2, wn = warp & 3;
    int g = lane >> 2, tg = lane & 3;
    int m0 = blockIdx.x * 128;
    int n0 = blockIdx.y * 128;
    int lrow = t >> 1, lpart = (t & 1) * 16;

    float c[4][4][4];
#pragma unroll
    for (int i = 0; i < 4; i++)
#pragma unroll
        for (int j = 0; j < 4; j++)
#pragma unroll
            for (int q = 0; q < 4; q++) c[i][j][q] = 0.f;

    for (int kc = 0; kc < DTP / 32; kc++) {
        int k0g = kc * 32;
        {
            const float4* src = reinterpret_cast<const float4*>(&g_z[(m0 + lrow) * DTP + k0g + lpart]);
#pragma unroll
            for (int q = 0; q < 4; q++) {
                float4 v = src[q];
                As[lrow * SAP + lpart + q * 4 + 0] = __float_as_uint(v.x);
                As[lrow * SAP + lpart + q * 4 + 1] = __float_as_uint(v.y);
                As[lrow * SAP + lpart + q * 4 + 2] = __float_as_uint(v.z);
                As[lrow * SAP + lpart + q * 4 + 3] = __float_as_uint(v.w);
            }
        }
        {
            int n = n0 + lrow;
            if (n < N_TYPE) {
                const float4* src = reinterpret_cast<const float4*>(&g_twc[n * DTP + k0g + lpart]);
#pragma unroll
                for (int q = 0; q < 4; q++) {
                    float4 v = src[q];
                    Bs[lrow * SAP + lpart + q * 4 + 0] = __float_as_uint(v.x);
                    Bs[lrow * SAP + lpart + q * 4 + 1] = __float_as_uint(v.y);
                    Bs[lrow * SAP + lpart + q * 4 + 2] = __float_as_uint(v.z);
                    Bs[lrow * SAP + lpart + q * 4 + 3] = __float_as_uint(v.w);
                }
            } else {
#pragma unroll
                for (int q = 0; q < 16; q++) Bs[lrow * SAP + lpart + q] = 0u;
            }
        }
        __syncthreads();
#pragma unroll
        for (int kk = 0; kk < 4; kk++) {
            int k0 = kk * 8;
            unsigned ar[4][4], br[4][2];
#pragma unroll
            for (int mt = 0; mt < 4; mt++) {
                int r = wm * 64 + mt * 16 + g;
                ar[mt][0] = As[r * SAP + k0 + tg];
                ar[mt][1] = As[(r + 8) * SAP + k0 + tg];
                ar[mt][2] = As[r * SAP + k0 + tg + 4];
                ar[mt][3] = As[(r + 8) * SAP + k0 + tg + 4];
            }
#pragma unroll
            for (int nt = 0; nt < 4; nt++) {
                int r = wn * 32 + nt * 8 + g;
                br[nt][0] = Bs[r * SAP + k0 + tg];
                br[nt][1] = Bs[r * SAP + k0 + tg + 4];
            }
#pragma unroll
            for (int mt = 0; mt < 4; mt++)
#pragma unroll
                for (int nt = 0; nt < 4; nt++) mma_tf32(c[mt][nt], ar[mt], br[nt]);
        }
        __syncthreads();
    }
#pragma unroll
    for (int mt = 0; mt < 4; mt++) {
        int mrow = m0 + wm * 64 + mt * 16 + g;
#pragma unroll
        for (int nt = 0; nt < 4; nt++) {
            int n = n0 + wn * 32 + nt * 8 + 2 * tg;
            if (n < N_TYPE) {
                float b0 = bbias[n];
                out[mrow * N_TYPE + n] = 1.f / (1.f + expf(-(c[mt][nt][0] + b0)));
                out[(mrow + 8) * N_TYPE + n] = 1.f / (1.f + expf(-(c[mt][nt][2] + b0)));
            }
            if (n + 1 < N_TYPE) {
                float b1 = bbias[n + 1];
                out[mrow * N_TYPE + n + 1] = 1.f / (1.f + expf(-(c[mt][nt][1] + b1)));
                out[(mrow + 8) * N_TYPE + n + 1] = 1.f / (1.f + expf(-(c[mt][nt][3] + b1)));
            }
        }
    }
}

// ---------------- launch ----------------
extern "C" void kernel_launch(void* const* d_in, const int* in_sizes, int n_in,
                              void* d_out, int out_size) {
    const int* xb = (const int*)d_in[0];
    const int* ei = (const int*)d_in[1];
    const int* et = (const int*)d_in[2];
    const float* Ew = (const float*)d_in[3];
    const float* Rw = (const float*)d_in[4];
    const float* Tw = (const float*)d_in[5];
    const float* Wf = (const float*)d_in[6];
    const float* av = (const float*)d_in[7];
    const float* cw = (const float*)d_in[8];
    const float* cb = (const float*)d_in[9];
    const float* b1g = (const float*)d_in[10];
    const float* b1b = (const float*)d_in[11];
    const float* b3g = (const float*)d_in[12];
    const float* b3b = (const float*)d_in[13];
    const float* b2g = (const float*)d_in[14];
    const float* b2b = (const float*)d_in[15];
    const float* fcw = (const float*)d_in[16];
    const float* fcb = (const float*)d_in[17];
    const float* bbias = (const float*)d_in[18];
    float* out = (float*)d_out;

    k_zero<<<512, 256>>>();
    k_flag<<<BATCH, NOUT>>>(xb);
    k_compact<<<(N_EDGE + 255) / 256, 256>>>(ei, et);
    k_wa<<<13, 256>>>(Wf, av);
    k_h16<<<N_ENT / 16, 128>>>(Ew, Wf);
    k_rproj<<<N_REL, NOUT>>>(Rw, Wf, av);
    k_score<<<512, 256>>>();
    k_agg<<<1024, 256>>>();
    k_gather<<<BATCH, NOUT>>>(xb);
    k_bn1fin<<<1, 1>>>(b1g, b1b);
    k_conv<<<BATCH, 256>>>(cw, cb);
    k_bn3fin<<<1, 32>>>(b3g, b3b);
    k_prep_fcw<<<(DT * FC_LEN + 255) / 256, 256>>>(fcw);
    {
        dim3 gg(BATCH / 128, 2);
        k_fc<<<gg, 256>>>(fcb);
    }
    k_bn2<<<DT, 128>>>(b2g, b2b);
    k_bn2apply<<<(BATCH * DTP + 255) / 256, 256>>>();
    k_prep_tw<<<(N_TYPE * DTP + 255) / 256, 256>>>(Tw);
    {
        dim3 gg(BATCH / 128, (N_TYPE + 127) / 128);
        k_out<<<gg, 256>>>(bbias, out);
    }
}

// round 11
// speedup vs baseline: 1.0772x; 1.0711x over previous
#include <cuda_runtime.h>
#include <math.h>

#define N_ENT 50000
#define N_REL 237
#define N_TYPE 4000
#define DE 100
#define NOUT 128
#define DT 200
#define DTP 224
#define N_EDGE 800000
#define BATCH 4096
#define NUM_FILT 32
#define CONV_W 60
#define POOL_W 30
#define FC_LEN 960
#define EPS 1e-5f

// ---------------- scratch ----------------
__device__ float g_hm[N_ENT];
__device__ float g_wa1[DE];
__device__ float g_wa2[DE];
__device__ float g_ra[N_REL];
__device__ int   g_flag[N_ENT];
__device__ float g_hdc[BATCH];
__device__ float g_denomc[BATCH];
__device__ float g_Cagg[BATCH * DE];
__device__ int   g_ecnt;
__device__ int   g_cs[N_EDGE];
__device__ int   g_cdp[N_EDGE];
__device__ int   g_ct[N_EDGE];
__device__ float g_ex[N_EDGE];
__device__ float g_e[BATCH * NOUT];
__device__ float g_conv[BATCH * NUM_FILT * CONV_W];
__device__ float g_y[BATCH * DT];
__device__ float g_z[BATCH * DTP];              // relu(bn2), tf32-rounded, K-padded
__device__ float g_twc[N_TYPE * DTP];           // Tw tf32-rounded, K-padded
__device__ float g_fcwc[DT * FC_LEN];           // fc_w tf32-rounded
__device__ float g_bn1[4];
__device__ float g_bn3sum[NUM_FILT], g_bn3ss[NUM_FILT];
__device__ float g_bn3sc[NUM_FILT], g_bn3sh[NUM_FILT];
__device__ unsigned g_c1, g_c3;

// ---------------- helpers ----------------
__device__ __forceinline__ unsigned f2tf(float x) {
    unsigned r;
    asm("cvt.rna.tf32.f32 %0, %1;" : "=r"(r) : "f"(x));
    return r;
}

__device__ __forceinline__ void mma_tf32(float c[4], const unsigned a[4], const unsigned b[2]) {
    asm volatile(
        "mma.sync.aligned.m16n8k8.row.col.f32.tf32.tf32.f32 "
        "{%0,%1,%2,%3}, {%4,%5,%6,%7}, {%8,%9}, {%0,%1,%2,%3};"
        : "+f"(c[0]), "+f"(c[1]), "+f"(c[2]), "+f"(c[3])
        : "r"(a[0]), "r"(a[1]), "r"(a[2]), "r"(a[3]), "r"(b[0]), "r"(b[1]));
}

// ---------------- small kernels ----------------

// wa1 = W_f @ a1, wa2 = W_f @ a2  (warp per k-row)
__global__ void k_wa(const float* __restrict__ Wf, const float* __restrict__ av) {
    int k = blockIdx.x * 8 + (threadIdx.x >> 5);
    int lane = threadIdx.x & 31;
    if (k >= DE) return;
    float s1 = 0.f, s2 = 0.f;
#pragma unroll
    for (int q = 0; q < 4; q++) {
        int j = lane + q * 32;
        float w = Wf[k * NOUT + j];
        s1 += w * av[j];
        s2 += w * av[NOUT + j];
    }
#pragma unroll
    for (int o = 16; o > 0; o >>= 1) {
        s1 += __shfl_xor_sync(0xffffffffu, s1, o);
        s2 += __shfl_xor_sync(0xffffffffu, s2, o);
    }
    if (lane == 0) { g_wa1[k] = s1; g_wa2[k] = s2; }
}

__global__ void k_zero() {
    int tid = blockIdx.x * blockDim.x + threadIdx.x;
    int stride = gridDim.x * blockDim.x;
    for (int i = tid; i < N_ENT; i += stride) g_flag[i] = 0;
    if (tid == 0) { g_ecnt = 0; g_c1 = 0u; g_c3 = 0u; }
    if (tid < 2) g_bn1[tid] = 0.f;
    for (int i = tid; i < NUM_FILT; i += stride) { g_bn3sum[i] = 0.f; g_bn3ss[i] = 0.f; }
}

// flag dst nodes (value b+1), zero Cagg row + denom, compute hd for the row.
__global__ void k_flag(const int* __restrict__ xb, const float* __restrict__ Ew) {
    int b = blockIdx.x, t = threadIdx.x;
    int n = xb[b];
    if (t == 0) g_flag[n] = b + 1;       // duplicate-n race: any winner is fine
    if (t >= 32 && t - 32 < DE) g_Cagg[b * DE + (t - 32)] = 0.f;
    if (t == 32 + DE) g_denomc[b] = 0.f;
    if (t < 32) {
        float s = 0.f;
        for (int k = t; k < DE; k += 32) s += Ew[n * DE + k] * g_wa1[k];
#pragma unroll
        for (int o = 16; o > 0; o >>= 1) s += __shfl_xor_sync(0xffffffffu, s, o);
        if (t == 0) g_hdc[b] = s;
    }
}

// hm[n] = Ew[n].wa2 for all nodes ; ra[r] = Rw[r].wa2  (warp per row)
__global__ void k_hmra(const float* __restrict__ Ew, const float* __restrict__ Rw) {
    int idx = blockIdx.x * 8 + (threadIdx.x >> 5);
    int lane = threadIdx.x & 31;
    if (idx < N_ENT) {
        float s = 0.f;
        for (int k = lane; k < DE; k += 32) s += Ew[idx * DE + k] * g_wa2[k];
#pragma unroll
        for (int o = 16; o > 0; o >>= 1) s += __shfl_xor_sync(0xffffffffu, s, o);
        if (lane == 0) g_hm[idx] = s;
    } else if (idx < N_ENT + N_REL) {
        int r = idx - N_ENT;
        float s = 0.f;
        for (int k = lane; k < DE; k += 32) s += Rw[r * DE + k] * g_wa2[k];
#pragma unroll
        for (int o = 16; o > 0; o >>= 1) s += __shfl_xor_sync(0xffffffffu, s, o);
        if (lane == 0) g_ra[r] = s;
    }
}

// compact edges whose dst is flagged (warp-aggregated atomics); store compact pos
__global__ void k_compact(const int* __restrict__ ei, const int* __restrict__ et) {
    int e = blockIdx.x * blockDim.x + threadIdx.x;
    int lane = threadIdx.x & 31;
    int f = 0;
    bool pred = false;
    if (e < N_EDGE) {
        f = g_flag[ei[N_EDGE + e]];
        pred = (f != 0);
    }
    unsigned mask = __ballot_sync(0xffffffffu, pred);
    if (mask == 0) return;
    int leader = __ffs(mask) - 1;
    int base = 0;
    if (lane == leader) base = atomicAdd(&g_ecnt, __popc(mask));
    base = __shfl_sync(0xffffffffu, base, leader);
    if (pred) {
        int pos = base + __popc(mask & ((1u << lane) - 1u));
        g_cs[pos] = ei[e];
        g_cdp[pos] = f - 1;
        g_ct[pos] = et[e];
    }
}

__global__ void k_score() {
    int tid = blockIdx.x * blockDim.x + threadIdx.x;
    int stride = gridDim.x * blockDim.x;
    int cnt = g_ecnt;
    for (int e = tid; e < cnt; e += stride) {
        int src = g_cs[e], p = g_cdp[e], t = g_ct[e];
        float s = g_hdc[p] + g_hm[src] - g_ra[t];
        s = (s >= 0.f) ? s : 0.2f * s;
        float ex = expf(s);
        g_ex[e] = ex;
        atomicAdd(&g_denomc[p], ex);
    }
}

// warp-per-edge scatter in DE space: Cagg[p] += att * (Ew[src] - Rw[t])
__global__ void k_agg(const float* __restrict__ Ew, const float* __restrict__ Rw) {
    int w = (blockIdx.x * blockDim.x + threadIdx.x) >> 5;
    int nwarp = (gridDim.x * blockDim.x) >> 5;
    int lane = threadIdx.x & 31;
    int cnt = g_ecnt;
    for (int e = w; e < cnt; e += nwarp) {
        int src = g_cs[e], p = g_cdp[e], t = g_ct[e];
        float wt = g_ex[e] / (g_denomc[p] + 1e-16f);
        if (lane < DE / 4) {
            float4 a = reinterpret_cast<const float4*>(&Ew[src * DE])[lane];
            float4 b = reinterpret_cast<const float4*>(&Rw[t * DE])[lane];
            float4 v;
            v.x = wt * (a.x - b.x); v.y = wt * (a.y - b.y);
            v.z = wt * (a.z - b.z); v.w = wt * (a.w - b.w);
            float* pp = &g_Cagg[p * DE + lane * 4];
            asm volatile("red.global.add.v4.f32 [%0], {%1,%2,%3,%4};"
                         :: "l"(pp), "f"(v.x), "f"(v.y), "f"(v.z), "f"(v.w) : "memory");
        }
    }
}

// gather Cagg rows, project through Wf, elu, bn1 stats (+ last-block finalize)
__global__ void k_gatherproj(const int* __restrict__ xb, const float* __restrict__ Wf,
                             const float* __restrict__ b1g, const float* __restrict__ b1b) {
    int b0 = blockIdx.x * 16;
    int t = threadIdx.x;
    __shared__ float C[16][DE];
    __shared__ int posr[16];
    __shared__ float r1[128], r2[128];
    if (t < 16) posr[t] = g_flag[xb[b0 + t]] - 1;
    __syncthreads();
    for (int i = t; i < 16 * DE; i += 128) {
        int r = i / DE, k = i % DE;
        C[r][k] = g_Cagg[posr[r] * DE + k];
    }
    __syncthreads();
    int jl = t & 31, ng = t >> 5;
    float acc[4][4];
#pragma unroll
    for (int a = 0; a < 4; a++)
#pragma unroll
        for (int b = 0; b < 4; b++) acc[a][b] = 0.f;
    for (int k = 0; k < DE; k++) {
        float w0 = Wf[k * NOUT + jl];
        float w1 = Wf[k * NOUT + jl + 32];
        float w2 = Wf[k * NOUT + jl + 64];
        float w3 = Wf[k * NOUT + jl + 96];
#pragma unroll
        for (int nn = 0; nn < 4; nn++) {
            float e = C[ng * 4 + nn][k];
            acc[nn][0] += e * w0;
            acc[nn][1] += e * w1;
            acc[nn][2] += e * w2;
            acc[nn][3] += e * w3;
        }
    }
    float s = 0.f, ss = 0.f;
#pragma unroll
    for (int nn = 0; nn < 4; nn++)
#pragma unroll
        for (int q = 0; q < 4; q++) {
            float v = acc[nn][q];
            float e = (v > 0.f) ? v : expm1f(v);
            g_e[(b0 + ng * 4 + nn) * NOUT + q * 32 + jl] = e;
            s += e; ss += e * e;
        }
    r1[t] = s; r2[t] = ss;
    __syncthreads();
    for (int o = 64; o > 0; o >>= 1) {
        if (t < o) { r1[t] += r1[t + o]; r2[t] += r2[t + o]; }
        __syncthreads();
    }
    if (t == 0) { atomicAdd(&g_bn1[0], r1[0]); atomicAdd(&g_bn1[1], r2[0]); }
    __threadfence();
    __shared__ int lastf;
    if (t == 0) lastf = (atomicAdd(&g_c1, 1u) == gridDim.x - 1) ? 1 : 0;
    __syncthreads();
    if (lastf && t == 0) {
        float cnt = (float)(BATCH * NOUT);
        float mean = g_bn1[0] / cnt;
        float var = g_bn1[1] / cnt - mean * mean;
        float inv = rsqrtf(var + EPS);
        float sc = b1g[0] * inv;
        g_bn1[2] = sc;
        g_bn1[3] = b1b[0] - sc * mean;
    }
}

// conv (bn1 folded into input) + conv_b ; bn3 stats (+ last-block finalize)
__global__ void k_conv(const float* __restrict__ cw, const float* __restrict__ cb,
                       const float* __restrict__ b3g, const float* __restrict__ b3b) {
    int b = blockIdx.x, tid = threadIdx.x;
    __shared__ float es[NOUT];
    __shared__ float wsm[NUM_FILT * 9];
    __shared__ float co[NUM_FILT * CONV_W];
    float sc = g_bn1[2], sh = g_bn1[3];
    if (tid < NOUT) es[tid] = sc * g_e[b * NOUT + tid] + sh;
    for (int i = tid; i < NUM_FILT * 9; i += blockDim.x) wsm[i] = cw[i];
    __syncthreads();
    for (int i = tid; i < NUM_FILT * CONV_W; i += blockDim.x) {
        int c = i / CONV_W, w = i % CONV_W;
        float acc = cb[c];
#pragma unroll
        for (int k = 0; k < 9; k++) acc += wsm[c * 9 + k] * es[2 * w + k];
        co[i] = acc;
        g_conv[b * NUM_FILT * CONV_W + i] = acc;
    }
    __syncthreads();
    if (tid < NUM_FILT) {
        float s = 0.f, ss = 0.f;
        for (int w = 0; w < CONV_W; w++) {
            float v = co[tid * CONV_W + w];
            s += v; ss += v * v;
        }
        atomicAdd(&g_bn3sum[tid], s);
        atomicAdd(&g_bn3ss[tid], ss);
    }
    __threadfence();
    __shared__ int lastf;
    if (tid == 0) lastf = (atomicAdd(&g_c3, 1u) == gridDim.x - 1) ? 1 : 0;
    __syncthreads();
    if (lastf && tid < NUM_FILT) {
        float cnt = (float)(BATCH * CONV_W);
        float mean = g_bn3sum[tid] / cnt;
        float var = g_bn3ss[tid] / cnt - mean * mean;
        float inv = rsqrtf(var + EPS);
        float scc = b3g[tid] * inv;
        g_bn3sc[tid] = scc;
        g_bn3sh[tid] = b3b[tid] - scc * mean;
    }
}

// fused prep: fcw + Tw tf32 copies (Tw K-padded)
__global__ void k_prep(const float* __restrict__ fcw, const float* __restrict__ Tw) {
    int i = blockIdx.x * blockDim.x + threadIdx.x;
    if (i < DT * FC_LEN) {
        g_fcwc[i] = __uint_as_float(f2tf(fcw[i]));
    } else {
        int j = i - DT * FC_LEN;
        if (j < N_TYPE * DTP) {
            int n = j / DTP, k = j % DTP;
            float v = (k < DT) ? Tw[n * DT + k] : 0.f;
            g_twc[j] = __uint_as_float(f2tf(v));
        }
    }
}

// ---------------- tf32 GEMM 1: fc ----------------
#define SAP 36
__global__ void __launch_bounds__(256) k_fc(const float* __restrict__ fcb) {
    __shared__ unsigned As[128 * SAP];
    __shared__ unsigned Bs[128 * SAP];
    int t = threadIdx.x;
    int warp = t >> 5, lane = t & 31;
    int wm = warp >> 2, wn = warp & 3;
    int g = lane >> 2, tg = lane & 3;
    int m0 = blockIdx.x * 128;
    int n0 = blockIdx.y * 128;
    int lrow = t >> 1, lpart = (t & 1) * 16;

    float c[4][4][4];
#pragma unroll
    for (int i = 0; i < 4; i++)
#pragma unroll
        for (int j = 0; j < 4; j++)
#pragma unroll
            for (int q = 0; q < 4; q++) c[i][j][q] = 0.f;

    for (int kc = 0; kc < FC_LEN / 32; kc++) {
        int k0g = kc * 32;
        {
            int b = m0 + lrow;
            const float* crow = &g_conv[b * (NUM_FILT * CONV_W)];
#pragma unroll
            for (int q = 0; q < 16; q++) {
                int kk = k0g + lpart + q;
                int ch = kk / POOL_W, w = kk % POOL_W;
                float sc = g_bn3sc[ch], sh = g_bn3sh[ch];
                float x0 = crow[ch * CONV_W + 2 * w];
                float x1 = crow[ch * CONV_W + 2 * w + 1];
                float v = fmaxf(fmaxf(sc * x0 + sh, sc * x1 + sh), 0.f);
                As[lrow * SAP + lpart + q] = f2tf(v);
            }
        }
        {
            int n = n0 + lrow;
            if (n < DT) {
                const float4* src = reinterpret_cast<const float4*>(&g_fcwc[n * FC_LEN + k0g + lpart]);
#pragma unroll
                for (int q = 0; q < 4; q++) {
                    float4 v = src[q];
                    Bs[lrow * SAP + lpart + q * 4 + 0] = __float_as_uint(v.x);
                    Bs[lrow * SAP + lpart + q * 4 + 1] = __float_as_uint(v.y);
                    Bs[lrow * SAP + lpart + q * 4 + 2] = __float_as_uint(v.z);
                    Bs[lrow * SAP + lpart + q * 4 + 3] = __float_as_uint(v.w);
                }
            } else {
#pragma unroll
                for (int q = 0; q < 16; q++) Bs[lrow * SAP + lpart + q] = 0u;
            }
        }
        __syncthreads();
#pragma unroll
        for (int kk = 0; kk < 4; kk++) {
            int k0 = kk * 8;
            unsigned ar[4][4], br[4][2];
#pragma unroll
            for (int mt = 0; mt < 4; mt++) {
                int r = wm * 64 + mt * 16 + g;
                ar[mt][0] = As[r * SAP + k0 + tg];
                ar[mt][1] = As[(r + 8) * SAP + k0 + tg];
                ar[mt][2] = As[r * SAP + k0 + tg + 4];
                ar[mt][3] = As[(r + 8) * SAP + k0 + tg + 4];
            }
#pragma unroll
            for (int nt = 0; nt < 4; nt++) {
                int r = wn * 32 + nt * 8 + g;
                br[nt][0] = Bs[r * SAP + k0 + tg];
                br[nt][1] = Bs[r * SAP + k0 + tg + 4];
            }
#pragma unroll
            for (int mt = 0; mt < 4; mt++)
#pragma unroll
                for (int nt = 0; nt < 4; nt++) mma_tf32(c[mt][nt], ar[mt], br[nt]);
        }
        __syncthreads();
    }
#pragma unroll
    for (int mt = 0; mt < 4; mt++) {
        int mrow = m0 + wm * 64 + mt * 16 + g;
#pragma unroll
        for (int nt = 0; nt < 4; nt++) {
            int n = n0 + wn * 32 + nt * 8 + 2 * tg;
            if (n < DT)     g_y[mrow * DT + n]           = c[mt][nt][0] + fcb[n];
            if (n + 1 < DT) g_y[mrow * DT + n + 1]       = c[mt][nt][1] + fcb[n + 1];
            if (n < DT)     g_y[(mrow + 8) * DT + n]     = c[mt][nt][2] + fcb[n];
            if (n + 1 < DT) g_y[(mrow + 8) * DT + n + 1] = c[mt][nt][3] + fcb[n + 1];
        }
    }
}

// bn2 stats + apply fused: one block per z column (incl. zero-padding cols)
__global__ void k_bn2(const float* __restrict__ g, const float* __restrict__ b) {
    int k = blockIdx.x, tid = threadIdx.x;
    if (k >= DT) {
        for (int i = tid; i < BATCH; i += 128) g_z[i * DTP + k] = 0.f;
        return;
    }
    __shared__ float r1[128], r2[128];
    __shared__ float scsh[2];
    float v[32];
    float s = 0.f, ss = 0.f;
#pragma unroll
    for (int i = 0; i < 32; i++) {
        v[i] = g_y[(tid + i * 128) * DT + k];
        s += v[i]; ss += v[i] * v[i];
    }
    r1[tid] = s; r2[tid] = ss;
    __syncthreads();
    for (int o = 64; o > 0; o >>= 1) {
        if (tid < o) { r1[tid] += r1[tid + o]; r2[tid] += r2[tid + o]; }
        __syncthreads();
    }
    if (tid == 0) {
        float cnt = (float)BATCH;
        float mean = r1[0] / cnt;
        float var = r2[0] / cnt - mean * mean;
        float inv = rsqrtf(var + EPS);
        float sc = g[k] * inv;
        scsh[0] = sc;
        scsh[1] = b[k] - sc * mean;
    }
    __syncthreads();
    float sc = scsh[0], sh = scsh[1];
#pragma unroll
    for (int i = 0; i < 32; i++) {
        float z = fmaxf(sc * v[i] + sh, 0.f);
        g_z[(tid + i * 128) * DTP + k] = __uint_as_float(f2tf(z));
    }
}

// ---------------- tf32 GEMM 2: out = sigmoid(Z @ Tw^T + bias) ----------------
__global__ void __launch_bounds__(256) k_out(const float* __restrict__ bbias,
                                             float* __restrict__ out) {
    __shared__ unsigned As[128 * SAP];
    __shared__ unsigned Bs[128 * SAP];
    int t = threadIdx.x;
    int warp = t >> 5, lane = t & 31;
    int wm = warp >> 2, wn = warp & 3;
    int g = lane >> 2, tg = lane & 3;
    int m0 = blockIdx.x * 128;
    int n0 = blockIdx.y * 128;
    int lrow = t >> 1, lpart = (t & 1) * 16;

    float c[4][4][4];
#pragma unroll
    for (int i = 0; i < 4; i++)
#pragma unroll
        for (int j = 0; j < 4; j++)
#pragma unroll
            for (int q = 0; q < 4; q++) c[i][j][q] = 0.f;

    for (int kc = 0; kc < DTP / 32; kc++) {
        int k0g = kc * 32;
        {
            const float4* src = reinterpret_cast<const float4*>(&g_z[(m0 + lrow) * DTP + k0g + lpart]);
#pragma unroll
            for (int q = 0; q < 4; q++) {
                float4 v = src[q];
                As[lrow * SAP + lpart + q * 4 + 0] = __float_as_uint(v.x);
                As[lrow * SAP + lpart + q * 4 + 1] = __float_as_uint(v.y);
                As[lrow * SAP + lpart + q * 4 + 2] = __float_as_uint(v.z);
                As[lrow * SAP + lpart + q * 4 + 3] = __float_as_uint(v.w);
            }
        }
        {
            int n = n0 + lrow;
            if (n < N_TYPE) {
                const float4* src = reinterpret_cast<const float4*>(&g_twc[n * DTP + k0g + lpart]);
#pragma unroll
                for (int q = 0; q < 4; q++) {
                    float4 v = src[q];
                    Bs[lrow * SAP + lpart + q * 4 + 0] = __float_as_uint(v.x);
                    Bs[lrow * SAP + lpart + q * 4 + 1] = __float_as_uint(v.y);
                    Bs[lrow * SAP + lpart + q * 4 + 2] = __float_as_uint(v.z);
                    Bs[lrow * SAP + lpart + q * 4 + 3] = __float_as_uint(v.w);
                }
            } else {
#pragma unroll
                for (int q = 0; q < 16; q++) Bs[lrow * SAP + lpart + q] = 0u;
            }
        }
        __syncthreads();
#pragma unroll
        for (int kk = 0; kk < 4; kk++) {
            int k0 = kk * 8;
            unsigned ar[4][4], br[4][2];
#pragma unroll
            for (int mt = 0; mt < 4; mt++) {
                int r = wm * 64 + mt * 16 + g;
                ar[mt][0] = As[r * SAP + k0 + tg];
                ar[mt][1] = As[(r + 8) * SAP + k0 + tg];
                ar[mt][2] = As[r * SAP + k0 + tg + 4];
                ar[mt][3] = As[(r + 8) * SAP + k0 + tg + 4];
            }
#pragma unroll
            for (int nt = 0; nt < 4; nt++) {
                int r = wn * 32 + nt * 8 + g;
                br[nt][0] = Bs[r * SAP + k0 + tg];
                br[nt][1] = Bs[r * SAP + k0 + tg + 4];
            }
#pragma unroll
            for (int mt = 0; mt < 4; mt++)
#pragma unroll
                for (int nt = 0; nt < 4; nt++) mma_tf32(c[mt][nt], ar[mt], br[nt]);
        }
        __syncthreads();
    }
#pragma unroll
    for (int mt = 0; mt < 4; mt++) {
        int mrow = m0 + wm * 64 + mt * 16 + g;
#pragma unroll
        for (int nt = 0; nt < 4; nt++) {
            int n = n0 + wn * 32 + nt * 8 + 2 * tg;
            if (n < N_TYPE) {
                float b0 = bbias[n];
                out[mrow * N_TYPE + n] = 1.f / (1.f + expf(-(c[mt][nt][0] + b0)));
                out[(mrow + 8) * N_TYPE + n] = 1.f / (1.f + expf(-(c[mt][nt][2] + b0)));
            }
            if (n + 1 < N_TYPE) {
                float b1 = bbias[n + 1];
                out[mrow * N_TYPE + n + 1] = 1.f / (1.f + expf(-(c[mt][nt][1] + b1)));
                out[(mrow + 8) * N_TYPE + n + 1] = 1.f / (1.f + expf(-(c[mt][nt][3] + b1)));
            }
        }
    }
}

// ---------------- launch ----------------
extern "C" void kernel_launch(void* const* d_in, const int* in_sizes, int n_in,
                              void* d_out, int out_size) {
    const int* xb = (const int*)d_in[0];
    const int* ei = (const int*)d_in[1];
    const int* et = (const int*)d_in[2];
    const float* Ew = (const float*)d_in[3];
    const float* Rw = (const float*)d_in[4];
    const float* Tw = (const float*)d_in[5];
    const float* Wf = (const float*)d_in[6];
    const float* av = (const float*)d_in[7];
    const float* cw = (const float*)d_in[8];
    const float* cb = (const float*)d_in[9];
    const float* b1g = (const float*)d_in[10];
    const float* b1b = (const float*)d_in[11];
    const float* b3g = (const float*)d_in[12];
    const float* b3b = (const float*)d_in[13];
    const float* b2g = (const float*)d_in[14];
    const float* b2b = (const float*)d_in[15];
    const float* fcw = (const float*)d_in[16];
    const float* fcb = (const float*)d_in[17];
    const float* bbias = (const float*)d_in[18];
    float* out = (float*)d_out;

    k_wa<<<13, 256>>>(Wf, av);
    k_zero<<<256, 256>>>();
    k_flag<<<BATCH, 160>>>(xb, Ew);
    k_hmra<<<(N_ENT + N_REL + 7) / 8, 256>>>(Ew, Rw);
    k_compact<<<(N_EDGE + 255) / 256, 256>>>(ei, et);
    k_score<<<512, 256>>>();
    k_agg<<<1024, 256>>>(Ew, Rw);
    k_gatherproj<<<BATCH / 16, 128>>>(xb, Wf, b1g, b1b);
    k_conv<<<BATCH, 256>>>(cw, cb, b3g, b3b);
    k_prep<<<(DT * FC_LEN + N_TYPE * DTP + 255) / 256, 256>>>(fcw, Tw);
    {
        dim3 gg(BATCH / 128, 2);
        k_fc<<<gg, 256>>>(fcb);
    }
    k_bn2<<<DTP, 128>>>(b2g, b2b);
    {
        dim3 gg(BATCH / 128, (N_TYPE + 127) / 128);
        k_out<<<gg, 256>>>(bbias, out);
    }
}

// round 12
// speedup vs baseline: 1.0880x; 1.0100x over previous
#include <cuda_runtime.h>
#include <math.h>

#define N_ENT 50000
#define N_REL 237
#define N_TYPE 4000
#define DE 100
#define NOUT 128
#define DT 200
#define DTP 224
#define N_EDGE 800000
#define BATCH 4096
#define NUM_FILT 32
#define CONV_W 60
#define POOL_W 30
#define FC_LEN 960
#define EPS 1e-5f

// ---------------- scratch ----------------
__device__ float g_hm[N_ENT];
__device__ float g_wa1[DE];
__device__ float g_wa2[DE];
__device__ float g_ra[N_REL];
__device__ int   g_flag[N_ENT];
__device__ float g_hdc[BATCH];
__device__ float g_denomc[BATCH];
__device__ float g_Cagg[BATCH * DE];
__device__ int   g_ecnt;
__device__ int   g_cs[N_EDGE];
__device__ int   g_cdp[N_EDGE];
__device__ int   g_ct[N_EDGE];
__device__ float g_ex[N_EDGE];
__device__ float g_e[BATCH * NOUT];
__device__ float g_conv[BATCH * NUM_FILT * CONV_W];
__device__ float g_y[BATCH * DT];
__device__ float g_z[BATCH * DTP];              // relu(bn2), tf32-rounded, K-padded
__device__ float g_twc[N_TYPE * DTP];           // Tw tf32-rounded, K-padded
__device__ float g_fcwc[DT * FC_LEN];           // fc_w tf32-rounded
__device__ float g_bn1[4];
__device__ float g_bn3sum[NUM_FILT], g_bn3ss[NUM_FILT];
__device__ float g_bn3sc[NUM_FILT], g_bn3sh[NUM_FILT];
__device__ unsigned g_c1, g_c3;

// ---------------- helpers ----------------
__device__ __forceinline__ unsigned f2tf(float x) {
    unsigned r;
    asm("cvt.rna.tf32.f32 %0, %1;" : "=r"(r) : "f"(x));
    return r;
}

__device__ __forceinline__ void mma_tf32(float c[4], const unsigned a[4], const unsigned b[2]) {
    asm volatile(
        "mma.sync.aligned.m16n8k8.row.col.f32.tf32.tf32.f32 "
        "{%0,%1,%2,%3}, {%4,%5,%6,%7}, {%8,%9}, {%0,%1,%2,%3};"
        : "+f"(c[0]), "+f"(c[1]), "+f"(c[2]), "+f"(c[3])
        : "r"(a[0]), "r"(a[1]), "r"(a[2]), "r"(a[3]), "r"(b[0]), "r"(b[1]));
}

// ---------------- small kernels ----------------

// wa1 = W_f @ a1, wa2 = W_f @ a2  (warp per k-row)
__global__ void k_wa(const float* __restrict__ Wf, const float* __restrict__ av) {
    int k = blockIdx.x * 8 + (threadIdx.x >> 5);
    int lane = threadIdx.x & 31;
    if (k >= DE) return;
    float s1 = 0.f, s2 = 0.f;
#pragma unroll
    for (int q = 0; q < 4; q++) {
        int j = lane + q * 32;
        float w = Wf[k * NOUT + j];
        s1 += w * av[j];
        s2 += w * av[NOUT + j];
    }
#pragma unroll
    for (int o = 16; o > 0; o >>= 1) {
        s1 += __shfl_xor_sync(0xffffffffu, s1, o);
        s2 += __shfl_xor_sync(0xffffffffu, s2, o);
    }
    if (lane == 0) { g_wa1[k] = s1; g_wa2[k] = s2; }
}

__global__ void k_zero() {
    int tid = blockIdx.x * blockDim.x + threadIdx.x;
    int stride = gridDim.x * blockDim.x;
    for (int i = tid; i < N_ENT; i += stride) g_flag[i] = 0;
    if (tid == 0) { g_ecnt = 0; g_c1 = 0u; g_c3 = 0u; }
    if (tid < 2) g_bn1[tid] = 0.f;
    for (int i = tid; i < NUM_FILT; i += stride) { g_bn3sum[i] = 0.f; g_bn3ss[i] = 0.f; }
}

// flag dst nodes (value b+1), zero Cagg row + denom, compute hd for the row.
__global__ void k_flag(const int* __restrict__ xb, const float* __restrict__ Ew) {
    int b = blockIdx.x, t = threadIdx.x;
    int n = xb[b];
    if (t == 0) g_flag[n] = b + 1;       // duplicate-n race: any winner is fine
    if (t >= 32 && t - 32 < DE) g_Cagg[b * DE + (t - 32)] = 0.f;
    if (t == 32 + DE) g_denomc[b] = 0.f;
    if (t < 32) {
        float s = 0.f;
        for (int k = t; k < DE; k += 32) s += Ew[n * DE + k] * g_wa1[k];
#pragma unroll
        for (int o = 16; o > 0; o >>= 1) s += __shfl_xor_sync(0xffffffffu, s, o);
        if (t == 0) g_hdc[b] = s;
    }
}

// hm[n] = Ew[n].wa2 for all nodes ; ra[r] = Rw[r].wa2  (warp per row)
__global__ void k_hmra(const float* __restrict__ Ew, const float* __restrict__ Rw) {
    int idx = blockIdx.x * 8 + (threadIdx.x >> 5);
    int lane = threadIdx.x & 31;
    if (idx < N_ENT) {
        float s = 0.f;
        for (int k = lane; k < DE; k += 32) s += Ew[idx * DE + k] * g_wa2[k];
#pragma unroll
        for (int o = 16; o > 0; o >>= 1) s += __shfl_xor_sync(0xffffffffu, s, o);
        if (lane == 0) g_hm[idx] = s;
    } else if (idx < N_ENT + N_REL) {
        int r = idx - N_ENT;
        float s = 0.f;
        for (int k = lane; k < DE; k += 32) s += Rw[r * DE + k] * g_wa2[k];
#pragma unroll
        for (int o = 16; o > 0; o >>= 1) s += __shfl_xor_sync(0xffffffffu, s, o);
        if (lane == 0) g_ra[r] = s;
    }
}

// compact edges whose dst is flagged (warp-aggregated atomics); store compact pos
__global__ void k_compact(const int* __restrict__ ei, const int* __restrict__ et) {
    int e = blockIdx.x * blockDim.x + threadIdx.x;
    int lane = threadIdx.x & 31;
    int f = 0;
    bool pred = false;
    if (e < N_EDGE) {
        f = g_flag[ei[N_EDGE + e]];
        pred = (f != 0);
    }
    unsigned mask = __ballot_sync(0xffffffffu, pred);
    if (mask == 0) return;
    int leader = __ffs(mask) - 1;
    int base = 0;
    if (lane == leader) base = atomicAdd(&g_ecnt, __popc(mask));
    base = __shfl_sync(0xffffffffu, base, leader);
    if (pred) {
        int pos = base + __popc(mask & ((1u << lane) - 1u));
        g_cs[pos] = ei[e];
        g_cdp[pos] = f - 1;
        g_ct[pos] = et[e];
    }
}

__global__ void k_score() {
    int tid = blockIdx.x * blockDim.x + threadIdx.x;
    int stride = gridDim.x * blockDim.x;
    int cnt = g_ecnt;
    for (int e = tid; e < cnt; e += stride) {
        int src = g_cs[e], p = g_cdp[e], t = g_ct[e];
        float s = g_hdc[p] + g_hm[src] - g_ra[t];
        s = (s >= 0.f) ? s : 0.2f * s;
        float ex = expf(s);
        g_ex[e] = ex;
        atomicAdd(&g_denomc[p], ex);
    }
}

// warp-per-edge scatter in DE space: Cagg[p] += att * (Ew[src] - Rw[t])
__global__ void k_agg(const float* __restrict__ Ew, const float* __restrict__ Rw) {
    int w = (blockIdx.x * blockDim.x + threadIdx.x) >> 5;
    int nwarp = (gridDim.x * blockDim.x) >> 5;
    int lane = threadIdx.x & 31;
    int cnt = g_ecnt;
    for (int e = w; e < cnt; e += nwarp) {
        int src = g_cs[e], p = g_cdp[e], t = g_ct[e];
        float wt = g_ex[e] / (g_denomc[p] + 1e-16f);
        if (lane < DE / 4) {
            float4 a = reinterpret_cast<const float4*>(&Ew[src * DE])[lane];
            float4 b = reinterpret_cast<const float4*>(&Rw[t * DE])[lane];
            float4 v;
            v.x = wt * (a.x - b.x); v.y = wt * (a.y - b.y);
            v.z = wt * (a.z - b.z); v.w = wt * (a.w - b.w);
            float* pp = &g_Cagg[p * DE + lane * 4];
            asm volatile("red.global.add.v4.f32 [%0], {%1,%2,%3,%4};"
                         :: "l"(pp), "f"(v.x), "f"(v.y), "f"(v.z), "f"(v.w) : "memory");
        }
    }
}

// gather Cagg rows, project through Wf, elu, bn1 stats (+ last-block finalize)
__global__ void k_gatherproj(const int* __restrict__ xb, const float* __restrict__ Wf,
                             const float* __restrict__ b1g, const float* __restrict__ b1b) {
    int b0 = blockIdx.x * 16;
    int t = threadIdx.x;
    __shared__ float C[16][DE];
    __shared__ int posr[16];
    __shared__ float r1[128], r2[128];
    if (t < 16) posr[t] = g_flag[xb[b0 + t]] - 1;
    __syncthreads();
    for (int i = t; i < 16 * DE; i += 128) {
        int r = i / DE, k = i % DE;
        C[r][k] = g_Cagg[posr[r] * DE + k];
    }
    __syncthreads();
    int jl = t & 31, ng = t >> 5;
    float acc[4][4];
#pragma unroll
    for (int a = 0; a < 4; a++)
#pragma unroll
        for (int b = 0; b < 4; b++) acc[a][b] = 0.f;
    for (int k = 0; k < DE; k++) {
        float w0 = Wf[k * NOUT + jl];
        float w1 = Wf[k * NOUT + jl + 32];
        float w2 = Wf[k * NOUT + jl + 64];
        float w3 = Wf[k * NOUT + jl + 96];
#pragma unroll
        for (int nn = 0; nn < 4; nn++) {
            float e = C[ng * 4 + nn][k];
            acc[nn][0] += e * w0;
            acc[nn][1] += e * w1;
            acc[nn][2] += e * w2;
            acc[nn][3] += e * w3;
        }
    }
    float s = 0.f, ss = 0.f;
#pragma unroll
    for (int nn = 0; nn < 4; nn++)
#pragma unroll
        for (int q = 0; q < 4; q++) {
            float v = acc[nn][q];
            float e = (v > 0.f) ? v : expm1f(v);
            g_e[(b0 + ng * 4 + nn) * NOUT + q * 32 + jl] = e;
            s += e; ss += e * e;
        }
    r1[t] = s; r2[t] = ss;
    __syncthreads();
    for (int o = 64; o > 0; o >>= 1) {
        if (t < o) { r1[t] += r1[t + o]; r2[t] += r2[t + o]; }
        __syncthreads();
    }
    if (t == 0) { atomicAdd(&g_bn1[0], r1[0]); atomicAdd(&g_bn1[1], r2[0]); }
    __threadfence();
    __shared__ int lastf;
    if (t == 0) lastf = (atomicAdd(&g_c1, 1u) == gridDim.x - 1) ? 1 : 0;
    __syncthreads();
    if (lastf && t == 0) {
        float cnt = (float)(BATCH * NOUT);
        float mean = g_bn1[0] / cnt;
        float var = g_bn1[1] / cnt - mean * mean;
        float inv = rsqrtf(var + EPS);
        float sc = b1g[0] * inv;
        g_bn1[2] = sc;
        g_bn1[3] = b1b[0] - sc * mean;
    }
}

// conv (bn1 folded into input) + conv_b ; bn3 stats (+ last-block finalize)
__global__ void k_conv(const float* __restrict__ cw, const float* __restrict__ cb,
                       const float* __restrict__ b3g, const float* __restrict__ b3b) {
    int b = blockIdx.x, tid = threadIdx.x;
    __shared__ float es[NOUT];
    __shared__ float wsm[NUM_FILT * 9];
    __shared__ float co[NUM_FILT * CONV_W];
    float sc = g_bn1[2], sh = g_bn1[3];
    if (tid < NOUT) es[tid] = sc * g_e[b * NOUT + tid] + sh;
    for (int i = tid; i < NUM_FILT * 9; i += blockDim.x) wsm[i] = cw[i];
    __syncthreads();
    for (int i = tid; i < NUM_FILT * CONV_W; i += blockDim.x) {
        int c = i / CONV_W, w = i % CONV_W;
        float acc = cb[c];
#pragma unroll
        for (int k = 0; k < 9; k++) acc += wsm[c * 9 + k] * es[2 * w + k];
        co[i] = acc;
        g_conv[b * NUM_FILT * CONV_W + i] = acc;
    }
    __syncthreads();
    if (tid < NUM_FILT) {
        float s = 0.f, ss = 0.f;
        for (int w = 0; w < CONV_W; w++) {
            float v = co[tid * CONV_W + w];
            s += v; ss += v * v;
        }
        atomicAdd(&g_bn3sum[tid], s);
        atomicAdd(&g_bn3ss[tid], ss);
    }
    __threadfence();
    __shared__ int lastf;
    if (tid == 0) lastf = (atomicAdd(&g_c3, 1u) == gridDim.x - 1) ? 1 : 0;
    __syncthreads();
    if (lastf && tid < NUM_FILT) {
        float cnt = (float)(BATCH * CONV_W);
        float mean = g_bn3sum[tid] / cnt;
        float var = g_bn3ss[tid] / cnt - mean * mean;
        float inv = rsqrtf(var + EPS);
        float scc = b3g[tid] * inv;
        g_bn3sc[tid] = scc;
        g_bn3sh[tid] = b3b[tid] - scc * mean;
    }
}

// fused prep: fcw + Tw tf32 copies (Tw K-padded)
__global__ void k_prep(const float* __restrict__ fcw, const float* __restrict__ Tw) {
    int i = blockIdx.x * blockDim.x + threadIdx.x;
    if (i < DT * FC_LEN) {
        g_fcwc[i] = __uint_as_float(f2tf(fcw[i]));
    } else {
        int j = i - DT * FC_LEN;
        if (j < N_TYPE * DTP) {
            int n = j / DTP, k = j % DTP;
            float v = (k < DT) ? Tw[n * DT + k] : 0.f;
            g_twc[j] = __uint_as_float(f2tf(v));
        }
    }
}

// ---------------- tf32 GEMM 1: fc ----------------
#define SAP 36
__global__ void __launch_bounds__(256) k_fc(const float* __restrict__ fcb) {
    __shared__ unsigned As[128 * SAP];
    __shared__ unsigned Bs[128 * SAP];
    int t = threadIdx.x;
    int warp = t >> 5, lane = t & 31;
    int wm = warp >> 2, wn = warp & 3;
    int g = lane >> 2, tg = lane & 3;
    int m0 = blockIdx.x * 128;
    int n0 = blockIdx.y * 128;
    int lrow = t >> 1, lpart = (t & 1) * 16;

    float c[4][4][4];
#pragma unroll
    for (int i = 0; i < 4; i++)
#pragma unroll
        for (int j = 0; j < 4; j++)
#pragma unroll
            for (int q = 0; q < 4; q++) c[i][j][q] = 0.f;

    for (int kc = 0; kc < FC_LEN / 32; kc++) {
        int k0g = kc * 32;
        {
            int b = m0 + lrow;
            const float* crow = &g_conv[b * (NUM_FILT * CONV_W)];
#pragma unroll
            for (int q = 0; q < 16; q++) {
                int kk = k0g + lpart + q;
                int ch = kk / POOL_W, w = kk % POOL_W;
                float sc = g_bn3sc[ch], sh = g_bn3sh[ch];
                float x0 = crow[ch * CONV_W + 2 * w];
                float x1 = crow[ch * CONV_W + 2 * w + 1];
                float v = fmaxf(fmaxf(sc * x0 + sh, sc * x1 + sh), 0.f);
                As[lrow * SAP + lpart + q] = f2tf(v);
            }
        }
        {
            int n = n0 + lrow;
            if (n < DT) {
                const float4* src = reinterpret_cast<const float4*>(&g_fcwc[n * FC_LEN + k0g + lpart]);
#pragma unroll
                for (int q = 0; q < 4; q++) {
                    float4 v = src[q];
                    Bs[lrow * SAP + lpart + q * 4 + 0] = __float_as_uint(v.x);
                    Bs[lrow * SAP + lpart + q * 4 + 1] = __float_as_uint(v.y);
                    Bs[lrow * SAP + lpart + q * 4 + 2] = __float_as_uint(v.z);
                    Bs[lrow * SAP + lpart + q * 4 + 3] = __float_as_uint(v.w);
                }
            } else {
#pragma unroll
                for (int q = 0; q < 16; q++) Bs[lrow * SAP + lpart + q] = 0u;
            }
        }
        __syncthreads();
#pragma unroll
        for (int kk = 0; kk < 4; kk++) {
            int k0 = kk * 8;
            unsigned ar[4][4], br[4][2];
#pragma unroll
            for (int mt = 0; mt < 4; mt++) {
                int r = wm * 64 + mt * 16 + g;
                ar[mt][0] = As[r * SAP + k0 + tg];
                ar[mt][1] = As[(r + 8) * SAP + k0 + tg];
                ar[mt][2] = As[r * SAP + k0 + tg + 4];
                ar[mt][3] = As[(r + 8) * SAP + k0 + tg + 4];
            }
#pragma unroll
            for (int nt = 0; nt < 4; nt++) {
                int r = wn * 32 + nt * 8 + g;
                br[nt][0] = Bs[r * SAP + k0 + tg];
                br[nt][1] = Bs[r * SAP + k0 + tg + 4];
            }
#pragma unroll
            for (int mt = 0; mt < 4; mt++)
#pragma unroll
                for (int nt = 0; nt < 4; nt++) mma_tf32(c[mt][nt], ar[mt], br[nt]);
        }
        __syncthreads();
    }
#pragma unroll
    for (int mt = 0; mt < 4; mt++) {
        int mrow = m0 + wm * 64 + mt * 16 + g;
#pragma unroll
        for (int nt = 0; nt < 4; nt++) {
            int n = n0 + wn * 32 + nt * 8 + 2 * tg;
            if (n < DT)     g_y[mrow * DT + n]           = c[mt][nt][0] + fcb[n];
            if (n + 1 < DT) g_y[mrow * DT + n + 1]       = c[mt][nt][1] + fcb[n + 1];
            if (n < DT)     g_y[(mrow + 8) * DT + n]     = c[mt][nt][2] + fcb[n];
            if (n + 1 < DT) g_y[(mrow + 8) * DT + n + 1] = c[mt][nt][3] + fcb[n + 1];
        }
    }
}

// bn2 stats + apply fused: one block per z column (incl. zero-padding cols)
__global__ void k_bn2(const float* __restrict__ g, const float* __restrict__ b) {
    int k = blockIdx.x, tid = threadIdx.x;
    if (k >= DT) {
        for (int i = tid; i < BATCH; i += 128) g_z[i * DTP + k] = 0.f;
        return;
    }
    __shared__ float r1[128], r2[128];
    __shared__ float scsh[2];
    float v[32];
    float s = 0.f, ss = 0.f;
#pragma unroll
    for (int i = 0; i < 32; i++) {
        v[i] = g_y[(tid + i * 128) * DT + k];
        s += v[i]; ss += v[i] * v[i];
    }
    r1[tid] = s; r2[tid] = ss;
    __syncthreads();
    for (int o = 64; o > 0; o >>= 1) {
        if (tid < o) { r1[tid] += r1[tid + o]; r2[tid] += r2[tid + o]; }
        __syncthreads();
    }
    if (tid == 0) {
        float cnt = (float)BATCH;
        float mean = r1[0] / cnt;
        float var = r2[0] / cnt - mean * mean;
        float inv = rsqrtf(var + EPS);
        float sc = g[k] * inv;
        scsh[0] = sc;
        scsh[1] = b[k] - sc * mean;
    }
    __syncthreads();
    float sc = scsh[0], sh = scsh[1];
#pragma unroll
    for (int i = 0; i < 32; i++) {
        float z = fmaxf(sc * v[i] + sh, 0.f);
        g_z[(tid + i * 128) * DTP + k] = __uint_as_float(f2tf(z));
    }
}

// ---------------- tf32 GEMM 2: out = sigmoid(Z @ Tw^T + bias) ----------------
__global__ void __launch_bounds__(256) k_out(const float* __restrict__ bbias,
                                             float* __restrict__ out) {
    __shared__ unsigned As[128 * SAP];
    __shared__ unsigned Bs[128 * SAP];
    int t = threadIdx.x;
    int warp = t >> 5, lane = t & 31;
    int wm = warp >> 2, wn = warp & 3;
    int g = lane >> 2, tg = lane & 3;
    int m0 = blockIdx.x * 128;
    int n0 = blockIdx.y * 128;
    int lrow = t >> 1, lpart = (t & 1) * 16;

    float c[4][4][4];
#pragma unroll
    for (int i = 0; i < 4; i++)
#pragma unroll
        for (int j = 0; j < 4; j++)
#pragma unroll
            for (int q = 0; q < 4; q++) c[i][j][q] = 0.f;

    for (int kc = 0; kc < DTP / 32; kc++) {
        int k0g = kc * 32;
        {
            const float4* src = reinterpret_cast<const float4*>(&g_z[(m0 + lrow) * DTP + k0g + lpart]);
#pragma unroll
            for (int q = 0; q < 4; q++) {
                float4 v = src[q];
                As[lrow * SAP + lpart + q * 4 + 0] = __float_as_uint(v.x);
                As[lrow * SAP + lpart + q * 4 + 1] = __float_as_uint(v.y);
                As[lrow * SAP + lpart + q * 4 + 2] = __float_as_uint(v.z);
                As[lrow * SAP + lpart + q * 4 + 3] = __float_as_uint(v.w);
            }
        }
        {
            int n = n0 + lrow;
            if (n < N_TYPE) {
                const float4* src = reinterpret_cast<const float4*>(&g_twc[n * DTP + k0g + lpart]);
#pragma unroll
                for (int q = 0; q < 4; q++) {
                    float4 v = src[q];
                    Bs[lrow * SAP + lpart + q * 4 + 0] = __float_as_uint(v.x);
                    Bs[lrow * SAP + lpart + q * 4 + 1] = __float_as_uint(v.y);
                    Bs[lrow * SAP + lpart + q * 4 + 2] = __float_as_uint(v.z);
                    Bs[lrow * SAP + lpart + q * 4 + 3] = __float_as_uint(v.w);
                }
            } else {
#pragma unroll
                for (int q = 0; q < 16; q++) Bs[lrow * SAP + lpart + q] = 0u;
            }
        }
        __syncthreads();
#pragma unroll
        for (int kk = 0; kk < 4; kk++) {
            int k0 = kk * 8;
            unsigned ar[4][4], br[4][2];
#pragma unroll
            for (int mt = 0; mt < 4; mt++) {
                int r = wm * 64 + mt * 16 + g;
                ar[mt][0] = As[r * SAP + k0 + tg];
                ar[mt][1] = As[(r + 8) * SAP + k0 + tg];
                ar[mt][2] = As[r * SAP + k0 + tg + 4];
                ar[mt][3] = As[(r + 8) * SAP + k0 + tg + 4];
            }
#pragma unroll
            for (int nt = 0; nt < 4; nt++) {
                int r = wn * 32 + nt * 8 + g;
                br[nt][0] = Bs[r * SAP + k0 + tg];
                br[nt][1] = Bs[r * SAP + k0 + tg + 4];
            }
#pragma unroll
            for (int mt = 0; mt < 4; mt++)
#pragma unroll
                for (int nt = 0; nt < 4; nt++) mma_tf32(c[mt][nt], ar[mt], br[nt]);
        }
        __syncthreads();
    }
#pragma unroll
    for (int mt = 0; mt < 4; mt++) {
        int mrow = m0 + wm * 64 + mt * 16 + g;
#pragma unroll
        for (int nt = 0; nt < 4; nt++) {
            int n = n0 + wn * 32 + nt * 8 + 2 * tg;
            if (n < N_TYPE) {
                float b0 = bbias[n];
                out[mrow * N_TYPE + n] = 1.f / (1.f + expf(-(c[mt][nt][0] + b0)));
                out[(mrow + 8) * N_TYPE + n] = 1.f / (1.f + expf(-(c[mt][nt][2] + b0)));
            }
            if (n + 1 < N_TYPE) {
                float b1 = bbias[n + 1];
                out[mrow * N_TYPE + n + 1] = 1.f / (1.f + expf(-(c[mt][nt][1] + b1)));
                out[(mrow + 8) * N_TYPE + n + 1] = 1.f / (1.f + expf(-(c[mt][nt][3] + b1)));
            }
        }
    }
}

// ---------------- launch ----------------
extern "C" void kernel_launch(void* const* d_in, const int* in_sizes, int n_in,
                              void* d_out, int out_size) {
    const int* xb = (const int*)d_in[0];
    const int* ei = (const int*)d_in[1];
    const int* et = (const int*)d_in[2];
    const float* Ew = (const float*)d_in[3];
    const float* Rw = (const float*)d_in[4];
    const float* Tw = (const float*)d_in[5];
    const float* Wf = (const float*)d_in[6];
    const float* av = (const float*)d_in[7];
    const float* cw = (const float*)d_in[8];
    const float* cb = (const float*)d_in[9];
    const float* b1g = (const float*)d_in[10];
    const float* b1b = (const float*)d_in[11];
    const float* b3g = (const float*)d_in[12];
    const float* b3b = (const float*)d_in[13];
    const float* b2g = (const float*)d_in[14];
    const float* b2b = (const float*)d_in[15];
    const float* fcw = (const float*)d_in[16];
    const float* fcb = (const float*)d_in[17];
    const float* bbias = (const float*)d_in[18];
    float* out = (float*)d_out;

    k_wa<<<13, 256>>>(Wf, av);
    k_zero<<<256, 256>>>();
    k_flag<<<BATCH, 160>>>(xb, Ew);
    k_hmra<<<(N_ENT + N_REL + 7) / 8, 256>>>(Ew, Rw);
    k_compact<<<(N_EDGE + 255) / 256, 256>>>(ei, et);
    k_score<<<512, 256>>>();
    k_agg<<<1024, 256>>>(Ew, Rw);
    k_gatherproj<<<BATCH / 16, 128>>>(xb, Wf, b1g, b1b);
    k_conv<<<BATCH, 256>>>(cw, cb, b3g, b3b);
    k_prep<<<(DT * FC_LEN + N_TYPE * DTP + 255) / 256, 256>>>(fcw, Tw);
    {
        dim3 gg(BATCH / 128, 2);
        k_fc<<<gg, 256>>>(fcb);
    }
    k_bn2<<<DTP, 128>>>(b2g, b2b);
    {
        dim3 gg(BATCH / 128, (N_TYPE + 127) / 128);
        k_out<<<gg, 256>>>(bbias, out);
    }
}

// round 13
// speedup vs baseline: 1.4535x; 1.3359x over previous
#include <cuda_runtime.h>
#include <math.h>

#define N_ENT 50000
#define N_REL 237
#define N_TYPE 4000
#define DE 100
#define NOUT 128
#define DT 200
#define DTP 224
#define N_EDGE 800000
#define BATCH 4096
#define NUM_FILT 32
#define CONV_W 60
#define POOL_W 30
#define FC_LEN 960
#define EPS 1e-5f

// GEMM geometry: block 128(M) x 256(N) x 32(K), 8 warps (2x4), warp tile 64x64
#define SAP 36
#define GEMM_SMEM (2 * (128 + 256) * SAP * 4)

// ---------------- scratch ----------------
__device__ float g_hm[N_ENT];
__device__ float g_wa1[DE];
__device__ float g_wa2[DE];
__device__ float g_ra[N_REL];
__device__ int   g_flag[N_ENT];
__device__ float g_hdc[BATCH];
__device__ float g_denomc[BATCH];
__device__ float g_Cagg[BATCH * DE];
__device__ int   g_ecnt;
__device__ int   g_cs[N_EDGE];
__device__ int   g_cdp[N_EDGE];
__device__ int   g_ct[N_EDGE];
__device__ float g_ex[N_EDGE];
__device__ float g_e[BATCH * NOUT];
__device__ float g_conv[BATCH * NUM_FILT * CONV_W];
__device__ float g_y[BATCH * DT];
__device__ float g_z[BATCH * DTP];
__device__ float g_twc[N_TYPE * DTP];
__device__ float g_fcwc[DT * FC_LEN];
__device__ float g_bn1[4];
__device__ float g_bn3sum[NUM_FILT], g_bn3ss[NUM_FILT];
__device__ float g_bn3sc[NUM_FILT], g_bn3sh[NUM_FILT];
__device__ float g_bn2sum[DT], g_bn2ss[DT];
__device__ float g_bn2sc[DT], g_bn2sh[DT];
__device__ unsigned g_c1, g_c2, g_c3;

// ---------------- helpers ----------------
__device__ __forceinline__ unsigned f2tf(float x) {
    unsigned r;
    asm("cvt.rna.tf32.f32 %0, %1;" : "=r"(r) : "f"(x));
    return r;
}

__device__ __forceinline__ void mma_tf32(float c[4], const unsigned a[4], const unsigned b[2]) {
    asm volatile(
        "mma.sync.aligned.m16n8k8.row.col.f32.tf32.tf32.f32 "
        "{%0,%1,%2,%3}, {%4,%5,%6,%7}, {%8,%9}, {%0,%1,%2,%3};"
        : "+f"(c[0]), "+f"(c[1]), "+f"(c[2]), "+f"(c[3])
        : "r"(a[0]), "r"(a[1]), "r"(a[2]), "r"(a[3]), "r"(b[0]), "r"(b[1]));
}

__device__ __forceinline__ void cp16(unsigned dst, const void* src) {
    asm volatile("cp.async.ca.shared.global [%0], [%1], 16;" :: "r"(dst), "l"(src));
}
__device__ __forceinline__ void cp_commit() { asm volatile("cp.async.commit_group;"); }
__device__ __forceinline__ void cp_wait1() { asm volatile("cp.async.wait_group 1;" ::: "memory"); }

// shared inner-loop: 64x64 warp tile, K=32 chunk
__device__ __forceinline__ void gemm_compute(const unsigned* __restrict__ A,
                                             const unsigned* __restrict__ B,
                                             float c[4][8][4], int wm, int wn,
                                             int g, int tg) {
#pragma unroll
    for (int kk = 0; kk < 4; kk++) {
        int k0 = kk * 8;
        unsigned ar[4][4];
#pragma unroll
        for (int mt = 0; mt < 4; mt++) {
            int rb = (wm * 64 + mt * 16 + g) * SAP + k0 + tg;
            ar[mt][0] = A[rb];
            ar[mt][1] = A[rb + 8 * SAP];
            ar[mt][2] = A[rb + 4];
            ar[mt][3] = A[rb + 8 * SAP + 4];
        }
#pragma unroll
        for (int nt = 0; nt < 8; nt++) {
            int nb = (wn * 64 + nt * 8 + g) * SAP + k0 + tg;
            unsigned br[2] = {B[nb], B[nb + 4]};
#pragma unroll
            for (int mt = 0; mt < 4; mt++) mma_tf32(c[mt][nt], ar[mt], br);
        }
    }
}

// ---------------- small kernels ----------------

// fused: wa vectors + all zero-init
__global__ void k_init(const float* __restrict__ Wf, const float* __restrict__ av) {
    int b = blockIdx.x, t = threadIdx.x;
    if (b < 13) {
        int k = b * 8 + (t >> 5);
        int lane = t & 31;
        if (k < DE) {
            float s1 = 0.f, s2 = 0.f;
#pragma unroll
            for (int q = 0; q < 4; q++) {
                int j = lane + q * 32;
                float w = Wf[k * NOUT + j];
                s1 += w * av[j];
                s2 += w * av[NOUT + j];
            }
#pragma unroll
            for (int o = 16; o > 0; o >>= 1) {
                s1 += __shfl_xor_sync(0xffffffffu, s1, o);
                s2 += __shfl_xor_sync(0xffffffffu, s2, o);
            }
            if (lane == 0) { g_wa1[k] = s1; g_wa2[k] = s2; }
        }
    }
    int tid = b * blockDim.x + t;
    int stride = gridDim.x * blockDim.x;
    for (int i = tid; i < N_ENT; i += stride) g_flag[i] = 0;
    if (tid == 0) { g_ecnt = 0; g_c1 = 0u; g_c2 = 0u; g_c3 = 0u; }
    if (tid < 2) g_bn1[tid] = 0.f;
    if (tid < NUM_FILT) { g_bn3sum[tid] = 0.f; g_bn3ss[tid] = 0.f; }
    if (tid < DT) { g_bn2sum[tid] = 0.f; g_bn2ss[tid] = 0.f; }
}

// flag dst nodes (value b+1), zero Cagg row + denom, compute hd for the row
__global__ void k_flag(const int* __restrict__ xb, const float* __restrict__ Ew) {
    int b = blockIdx.x, t = threadIdx.x;
    int n = xb[b];
    if (t == 0) g_flag[n] = b + 1;
    if (t >= 32 && t - 32 < DE) g_Cagg[b * DE + (t - 32)] = 0.f;
    if (t == 32 + DE) g_denomc[b] = 0.f;
    if (t < 32) {
        float s = 0.f;
        for (int k = t; k < DE; k += 32) s += Ew[n * DE + k] * g_wa1[k];
#pragma unroll
        for (int o = 16; o > 0; o >>= 1) s += __shfl_xor_sync(0xffffffffu, s, o);
        if (t == 0) g_hdc[b] = s;
    }
}

// hm[n] = Ew[n].wa2 ; ra[r] = Rw[r].wa2  (warp per row, float4)
__global__ void k_hmra(const float* __restrict__ Ew, const float* __restrict__ Rw) {
    int idx = blockIdx.x * 8 + (threadIdx.x >> 5);
    int lane = threadIdx.x & 31;
    float s = 0.f;
    if (idx < N_ENT) {
        if (lane < DE / 4) {
            float4 v = reinterpret_cast<const float4*>(Ew + (size_t)idx * DE)[lane];
            s = v.x * g_wa2[lane * 4] + v.y * g_wa2[lane * 4 + 1] +
                v.z * g_wa2[lane * 4 + 2] + v.w * g_wa2[lane * 4 + 3];
        }
#pragma unroll
        for (int o = 16; o > 0; o >>= 1) s += __shfl_xor_sync(0xffffffffu, s, o);
        if (lane == 0) g_hm[idx] = s;
    } else if (idx < N_ENT + N_REL) {
        int r = idx - N_ENT;
        if (lane < DE / 4) {
            float4 v = reinterpret_cast<const float4*>(Rw + (size_t)r * DE)[lane];
            s = v.x * g_wa2[lane * 4] + v.y * g_wa2[lane * 4 + 1] +
                v.z * g_wa2[lane * 4 + 2] + v.w * g_wa2[lane * 4 + 3];
        }
#pragma unroll
        for (int o = 16; o > 0; o >>= 1) s += __shfl_xor_sync(0xffffffffu, s, o);
        if (lane == 0) g_ra[r] = s;
    }
}

__global__ void k_compact(const int* __restrict__ ei, const int* __restrict__ et) {
    int e = blockIdx.x * blockDim.x + threadIdx.x;
    int lane = threadIdx.x & 31;
    int f = 0;
    bool pred = false;
    if (e < N_EDGE) {
        f = g_flag[ei[N_EDGE + e]];
        pred = (f != 0);
    }
    unsigned mask = __ballot_sync(0xffffffffu, pred);
    if (mask == 0) return;
    int leader = __ffs(mask) - 1;
    int base = 0;
    if (lane == leader) base = atomicAdd(&g_ecnt, __popc(mask));
    base = __shfl_sync(0xffffffffu, base, leader);
    if (pred) {
        int pos = base + __popc(mask & ((1u << lane) - 1u));
        g_cs[pos] = ei[e];
        g_cdp[pos] = f - 1;
        g_ct[pos] = et[e];
    }
}

__global__ void k_score() {
    int tid = blockIdx.x * blockDim.x + threadIdx.x;
    int stride = gridDim.x * blockDim.x;
    int cnt = g_ecnt;
    for (int e = tid; e < cnt; e += stride) {
        int src = g_cs[e], p = g_cdp[e], t = g_ct[e];
        float s = g_hdc[p] + g_hm[src] - g_ra[t];
        s = (s >= 0.f) ? s : 0.2f * s;
        float ex = expf(s);
        g_ex[e] = ex;
        atomicAdd(&g_denomc[p], ex);
    }
}

__global__ void k_agg(const float* __restrict__ Ew, const float* __restrict__ Rw) {
    int w = (blockIdx.x * blockDim.x + threadIdx.x) >> 5;
    int nwarp = (gridDim.x * blockDim.x) >> 5;
    int lane = threadIdx.x & 31;
    int cnt = g_ecnt;
    for (int e = w; e < cnt; e += nwarp) {
        int src = g_cs[e], p = g_cdp[e], t = g_ct[e];
        float wt = g_ex[e] / (g_denomc[p] + 1e-16f);
        if (lane < DE / 4) {
            float4 a = reinterpret_cast<const float4*>(&Ew[src * DE])[lane];
            float4 b = reinterpret_cast<const float4*>(&Rw[t * DE])[lane];
            float4 v;
            v.x = wt * (a.x - b.x); v.y = wt * (a.y - b.y);
            v.z = wt * (a.z - b.z); v.w = wt * (a.w - b.w);
            float* pp = &g_Cagg[p * DE + lane * 4];
            asm volatile("red.global.add.v4.f32 [%0], {%1,%2,%3,%4};"
                         :: "l"(pp), "f"(v.x), "f"(v.y), "f"(v.z), "f"(v.w) : "memory");
        }
    }
}

// gather Cagg rows, project through Wf, elu, bn1 stats (+ last-block finalize)
__global__ void k_gatherproj(const int* __restrict__ xb, const float* __restrict__ Wf,
                             const float* __restrict__ b1g, const float* __restrict__ b1b) {
    int b0 = blockIdx.x * 16;
    int t = threadIdx.x;
    __shared__ float C[16][DE];
    __shared__ int posr[16];
    __shared__ float r1[128], r2[128];
    if (t < 16) posr[t] = g_flag[xb[b0 + t]] - 1;
    __syncthreads();
    for (int i = t; i < 16 * DE; i += 128) {
        int r = i / DE, k = i % DE;
        C[r][k] = g_Cagg[posr[r] * DE + k];
    }
    __syncthreads();
    int jl = t & 31, ng = t >> 5;
    float acc[4][4];
#pragma unroll
    for (int a = 0; a < 4; a++)
#pragma unroll
        for (int b = 0; b < 4; b++) acc[a][b] = 0.f;
    for (int k = 0; k < DE; k++) {
        float w0 = Wf[k * NOUT + jl];
        float w1 = Wf[k * NOUT + jl + 32];
        float w2 = Wf[k * NOUT + jl + 64];
        float w3 = Wf[k * NOUT + jl + 96];
#pragma unroll
        for (int nn = 0; nn < 4; nn++) {
            float e = C[ng * 4 + nn][k];
            acc[nn][0] += e * w0;
            acc[nn][1] += e * w1;
            acc[nn][2] += e * w2;
            acc[nn][3] += e * w3;
        }
    }
    float s = 0.f, ss = 0.f;
#pragma unroll
    for (int nn = 0; nn < 4; nn++)
#pragma unroll
        for (int q = 0; q < 4; q++) {
            float v = acc[nn][q];
            float e = (v > 0.f) ? v : expm1f(v);
            g_e[(b0 + ng * 4 + nn) * NOUT + q * 32 + jl] = e;
            s += e; ss += e * e;
        }
    r1[t] = s; r2[t] = ss;
    __syncthreads();
    for (int o = 64; o > 0; o >>= 1) {
        if (t < o) { r1[t] += r1[t + o]; r2[t] += r2[t + o]; }
        __syncthreads();
    }
    if (t == 0) { atomicAdd(&g_bn1[0], r1[0]); atomicAdd(&g_bn1[1], r2[0]); }
    __threadfence();
    __shared__ int lastf;
    if (t == 0) lastf = (atomicAdd(&g_c1, 1u) == gridDim.x - 1) ? 1 : 0;
    __syncthreads();
    if (lastf && t == 0) {
        float cnt = (float)(BATCH * NOUT);
        float mean = g_bn1[0] / cnt;
        float var = g_bn1[1] / cnt - mean * mean;
        float inv = rsqrtf(var + EPS);
        float sc = b1g[0] * inv;
        g_bn1[2] = sc;
        g_bn1[3] = b1b[0] - sc * mean;
    }
}

// conv + conv_b ; bn3 stats (+ last-block finalize)
__global__ void k_conv(const float* __restrict__ cw, const float* __restrict__ cb,
                       const float* __restrict__ b3g, const float* __restrict__ b3b) {
    int b = blockIdx.x, tid = threadIdx.x;
    __shared__ float es[NOUT];
    __shared__ float wsm[NUM_FILT * 9];
    __shared__ float co[NUM_FILT * CONV_W];
    float sc = g_bn1[2], sh = g_bn1[3];
    if (tid < NOUT) es[tid] = sc * g_e[b * NOUT + tid] + sh;
    for (int i = tid; i < NUM_FILT * 9; i += blockDim.x) wsm[i] = cw[i];
    __syncthreads();
    for (int i = tid; i < NUM_FILT * CONV_W; i += blockDim.x) {
        int c = i / CONV_W, w = i % CONV_W;
        float acc = cb[c];
#pragma unroll
        for (int k = 0; k < 9; k++) acc += wsm[c * 9 + k] * es[2 * w + k];
        co[i] = acc;
        g_conv[b * NUM_FILT * CONV_W + i] = acc;
    }
    __syncthreads();
    if (tid < NUM_FILT) {
        float s = 0.f, ss = 0.f;
        for (int w = 0; w < CONV_W; w++) {
            float v = co[tid * CONV_W + w];
            s += v; ss += v * v;
        }
        atomicAdd(&g_bn3sum[tid], s);
        atomicAdd(&g_bn3ss[tid], ss);
    }
    __threadfence();
    __shared__ int lastf;
    if (tid == 0) lastf = (atomicAdd(&g_c3, 1u) == gridDim.x - 1) ? 1 : 0;
    __syncthreads();
    if (lastf && tid < NUM_FILT) {
        float cnt = (float)(BATCH * CONV_W);
        float mean = g_bn3sum[tid] / cnt;
        float var = g_bn3ss[tid] / cnt - mean * mean;
        float inv = rsqrtf(var + EPS);
        float scc = b3g[tid] * inv;
        g_bn3sc[tid] = scc;
        g_bn3sh[tid] = b3b[tid] - scc * mean;
    }
}

// prep: tf32 weight copies + zero g_y (split-K accumulator)
#define P1 (DT * FC_LEN)
#define P2 (N_TYPE * DTP)
#define P3 (BATCH * DT)
__global__ void k_prep(const float* __restrict__ fcw, const float* __restrict__ Tw) {
    int i = blockIdx.x * blockDim.x + threadIdx.x;
    if (i < P1) {
        g_fcwc[i] = __uint_as_float(f2tf(fcw[i]));
    } else if (i < P1 + P2) {
        int j = i - P1;
        int n = j / DTP, k = j % DTP;
        float v = (k < DT) ? Tw[n * DT + k] : 0.f;
        g_twc[j] = __uint_as_float(f2tf(v));
    } else if (i < P1 + P2 + P3) {
        g_y[i - P1 - P2] = 0.f;
    }
}

// ---------------- tf32 GEMM 1: fc (split-K, atomics into g_y) ----------------
__global__ void __launch_bounds__(256) k_fc() {
    extern __shared__ unsigned sm[];
    unsigned* As = sm;                       // [2][128*SAP]
    unsigned* Bs = sm + 2 * 128 * SAP;       // [2][256*SAP]
    int t = threadIdx.x;
    int warp = t >> 5, lane = t & 31;
    int wm = warp >> 2, wn = warp & 3;
    int g = lane >> 2, tg = lane & 3;
    int m0 = blockIdx.x * 128;
    int kbase = blockIdx.y * 256;
    int nch = (blockIdx.y < 3) ? 8 : 6;      // 960 = 256*3 + 192

    // zero invalid B rows (n >= 200) in both buffers
    for (int i = t; i < (256 - DT) * SAP; i += 256) {
        int r = DT + i / SAP, c = i % SAP;
        Bs[r * SAP + c] = 0u;
        Bs[256 * SAP + r * SAP + c] = 0u;
    }
    __syncthreads();

    float c[4][8][4];
#pragma unroll
    for (int i = 0; i < 4; i++)
#pragma unroll
        for (int j = 0; j < 8; j++)
#pragma unroll
            for (int q = 0; q < 4; q++) c[i][j][q] = 0.f;

    int arow = t >> 1, ahalf = (t & 1) * 16;
    const float* crow = g_conv + (size_t)(m0 + arow) * (NUM_FILT * CONV_W);

    // stage chunk kt into buffer buf
    auto stage = [&](int kt, int buf) {
        int k0g = kbase + kt * 32;
        // A: pooled+bn3+relu features (manual STS)
        unsigned* d = As + buf * 128 * SAP + arow * SAP + ahalf;
#pragma unroll
        for (int q = 0; q < 16; q++) {
            int kk = k0g + ahalf + q;
            int ch = kk / POOL_W, w = kk - ch * POOL_W;
            float sc = g_bn3sc[ch], sh = g_bn3sh[ch];
            float x0 = crow[ch * CONV_W + 2 * w];
            float x1 = crow[ch * CONV_W + 2 * w + 1];
            d[q] = f2tf(fmaxf(fmaxf(sc * x0 + sh, sc * x1 + sh), 0.f));
        }
        // B: fcw rows via cp.async
        if (t < DT) {
            const float* src = g_fcwc + (size_t)t * FC_LEN + k0g;
            unsigned db = (unsigned)__cvta_generic_to_shared(Bs + buf * 256 * SAP + t * SAP);
#pragma unroll
            for (int q = 0; q < 8; q++) cp16(db + q * 16, src + q * 4);
        }
    };

    stage(0, 0);
    cp_commit();
    for (int kt = 0; kt < nch; kt++) {
        if (kt + 1 < nch) stage(kt + 1, (kt + 1) & 1);
        cp_commit();
        cp_wait1();
        __syncthreads();
        gemm_compute(As + (kt & 1) * 128 * SAP, Bs + (kt & 1) * 256 * SAP, c, wm, wn, g, tg);
        __syncthreads();
    }

    // epilogue: atomic accumulate into g_y
#pragma unroll
    for (int mt = 0; mt < 4; mt++) {
        int mr = m0 + wm * 64 + mt * 16 + g;
#pragma unroll
        for (int nt = 0; nt < 8; nt++) {
            int n = wn * 64 + nt * 8 + 2 * tg;
            if (n < DT) {
                atomicAdd(&g_y[mr * DT + n], c[mt][nt][0]);
                atomicAdd(&g_y[mr * DT + n + 1], c[mt][nt][1]);
                atomicAdd(&g_y[(mr + 8) * DT + n], c[mt][nt][2]);
                atomicAdd(&g_y[(mr + 8) * DT + n + 1], c[mt][nt][3]);
            }
        }
    }
}

// y += bias (in place), bn2 stats, last-block finalize sc/sh
__global__ void k_ystat(const float* __restrict__ fcb, const float* __restrict__ b2g,
                        const float* __restrict__ b2b) {
    int r0 = blockIdx.x * 16, t = threadIdx.x;
    if (t < DT) {
        float bias = fcb[t];
        float s = 0.f, ss = 0.f;
#pragma unroll
        for (int i = 0; i < 16; i++) {
            float v = g_y[(r0 + i) * DT + t] + bias;
            g_y[(r0 + i) * DT + t] = v;
            s += v; ss += v * v;
        }
        atomicAdd(&g_bn2sum[t], s);
        atomicAdd(&g_bn2ss[t], ss);
    }
    __threadfence();
    __shared__ int lastf;
    if (t == 0) lastf = (atomicAdd(&g_c2, 1u) == gridDim.x - 1) ? 1 : 0;
    __syncthreads();
    if (lastf && t < DT) {
        float cnt = (float)BATCH;
        float mean = g_bn2sum[t] / cnt;
        float var = g_bn2ss[t] / cnt - mean * mean;
        float inv = rsqrtf(var + EPS);
        float sc = b2g[t] * inv;
        g_bn2sc[t] = sc;
        g_bn2sh[t] = b2b[t] - sc * mean;
    }
}

// z = relu(bn2(y)), tf32-rounded, K-padded
__global__ void k_apply() {
    int i = blockIdx.x * blockDim.x + threadIdx.x;
    if (i >= BATCH * DTP) return;
    int row = i / DTP, k = i - row * DTP;
    float v = 0.f;
    if (k < DT) {
        v = fmaxf(g_bn2sc[k] * g_y[row * DT + k] + g_bn2sh[k], 0.f);
        v = __uint_as_float(f2tf(v));
    }
    g_z[i] = v;
}

// ---------------- tf32 GEMM 2: out = sigmoid(Z @ Tw^T + bias) ----------------
__global__ void __launch_bounds__(256) k_out(const float* __restrict__ bbias,
                                             float* __restrict__ out) {
    extern __shared__ unsigned sm[];
    unsigned* As = sm;
    unsigned* Bs = sm + 2 * 128 * SAP;
    int t = threadIdx.x;
    int warp = t >> 5, lane = t & 31;
    int wm = warp >> 2, wn = warp & 3;
    int g = lane >> 2, tg = lane & 3;
    int m0 = blockIdx.x * 128;
    int n0 = blockIdx.y * 256;

    int inv0 = N_TYPE - n0;  // first invalid local B row
    if (inv0 < 256) {
        for (int i = t; i < (256 - inv0) * SAP; i += 256) {
            int r = inv0 + i / SAP, c = i % SAP;
            Bs[r * SAP + c] = 0u;
            Bs[256 * SAP + r * SAP + c] = 0u;
        }
    }
    __syncthreads();

    float c[4][8][4];
#pragma unroll
    for (int i = 0; i < 4; i++)
#pragma unroll
        for (int j = 0; j < 8; j++)
#pragma unroll
            for (int q = 0; q < 4; q++) c[i][j][q] = 0.f;

    int arow = t >> 1, ahalf = (t & 1) * 16;
    const float* asrc0 = g_z + (size_t)(m0 + arow) * DTP + ahalf;
    unsigned da0 = (unsigned)__cvta_generic_to_shared(As + arow * SAP + ahalf);
    bool bvalid = (n0 + t < N_TYPE);
    const float* bsrc0 = g_twc + (size_t)(n0 + t) * DTP;
    unsigned db0 = (unsigned)__cvta_generic_to_shared(Bs + t * SAP);

    auto stage = [&](int kt, int buf) {
        int k0g = kt * 32;
        unsigned da = da0 + buf * 128 * SAP * 4;
        const float* sa = asrc0 + k0g;
#pragma unroll
        for (int q = 0; q < 4; q++) cp16(da + q * 16, sa + q * 4);
        if (bvalid) {
            unsigned db = db0 + buf * 256 * SAP * 4;
            const float* sb = bsrc0 + k0g;
#pragma unroll
            for (int q = 0; q < 8; q++) cp16(db + q * 16, sb + q * 4);
        }
    };

    const int NK = DTP / 32;  // 7
    stage(0, 0);
    cp_commit();
    for (int kt = 0; kt < NK; kt++) {
        if (kt + 1 < NK) stage(kt + 1, (kt + 1) & 1);
        cp_commit();
        cp_wait1();
        __syncthreads();
        gemm_compute(As + (kt & 1) * 128 * SAP, Bs + (kt & 1) * 256 * SAP, c, wm, wn, g, tg);
        __syncthreads();
    }

#pragma unroll
    for (int mt = 0; mt < 4; mt++) {
        int mr = m0 + wm * 64 + mt * 16 + g;
#pragma unroll
        for (int nt = 0; nt < 8; nt++) {
            int n = n0 + wn * 64 + nt * 8 + 2 * tg;
            if (n < N_TYPE) {
                float b0 = bbias[n], b1 = bbias[n + 1];
                float2 o0, o1;
                o0.x = 1.f / (1.f + expf(-(c[mt][nt][0] + b0)));
                o0.y = 1.f / (1.f + expf(-(c[mt][nt][1] + b1)));
                o1.x = 1.f / (1.f + expf(-(c[mt][nt][2] + b0)));
                o1.y = 1.f / (1.f + expf(-(c[mt][nt][3] + b1)));
                *reinterpret_cast<float2*>(&out[(size_t)mr * N_TYPE + n]) = o0;
                *reinterpret_cast<float2*>(&out[(size_t)(mr + 8) * N_TYPE + n]) = o1;
            }
        }
    }
}

// ---------------- launch ----------------
extern "C" void kernel_launch(void* const* d_in, const int* in_sizes, int n_in,
                              void* d_out, int out_size) {
    const int* xb = (const int*)d_in[0];
    const int* ei = (const int*)d_in[1];
    const int* et = (const int*)d_in[2];
    const float* Ew = (const float*)d_in[3];
    const float* Rw = (const float*)d_in[4];
    const float* Tw = (const float*)d_in[5];
    const float* Wf = (const float*)d_in[6];
    const float* av = (const float*)d_in[7];
    const float* cw = (const float*)d_in[8];
    const float* cb = (const float*)d_in[9];
    const float* b1g = (const float*)d_in[10];
    const float* b1b = (const float*)d_in[11];
    const float* b3g = (const float*)d_in[12];
    const float* b3b = (const float*)d_in[13];
    const float* b2g = (const float*)d_in[14];
    const float* b2b = (const float*)d_in[15];
    const float* fcw = (const float*)d_in[16];
    const float* fcb = (const float*)d_in[17];
    const float* bbias = (const float*)d_in[18];
    float* out = (float*)d_out;

    cudaFuncSetAttribute(k_fc, cudaFuncAttributeMaxDynamicSharedMemorySize, GEMM_SMEM);
    cudaFuncSetAttribute(k_out, cudaFuncAttributeMaxDynamicSharedMemorySize, GEMM_SMEM);

    k_prep<<<(P1 + P2 + P3 + 255) / 256, 256>>>(fcw, Tw);
    k_init<<<256, 256>>>(Wf, av);
    k_flag<<<BATCH, 160>>>(xb, Ew);
    k_hmra<<<(N_ENT + N_REL + 7) / 8, 256>>>(Ew, Rw);
    k_compact<<<(N_EDGE + 255) / 256, 256>>>(ei, et);
    k_score<<<512, 256>>>();
    k_agg<<<1024, 256>>>(Ew, Rw);
    k_gatherproj<<<BATCH / 16, 128>>>(xb, Wf, b1g, b1b);
    k_conv<<<BATCH, 256>>>(cw, cb, b3g, b3b);
    {
        dim3 gg(BATCH / 128, 4);   // split-K = 4
        k_fc<<<gg, 256, GEMM_SMEM>>>();
    }
    k_ystat<<<BATCH / 16, 256>>>(fcb, b2g, b2b);
    k_apply<<<(BATCH * DTP + 255) / 256, 256>>>();
    {
        dim3 gg(BATCH / 128, (N_TYPE + 255) / 256);
        k_out<<<gg, 256, GEMM_SMEM>>>(bbias, out);
    }
}